// round 12
// baseline (speedup 1.0000x reference)
#include <cuda_runtime.h>
#include <cstdint>

#define NB   256   // batch
#define NL   200   // seq len
#define ND   256   // model dim
#define NH   16    // heads
#define NDH  16    // head dim

// ---------------- scratch (device globals: alloc-free) ----------------
__device__ float g_q[NB * NH * NL * NDH];    // [B,H,L,Dh]
__device__ float g_k[NB * NH * NL * NDH];
__device__ float g_v[NB * NH * NL * NDH];
__device__ float g_ctx[NB * NL * ND];        // [B,L,D]
__device__ float g_u[ND];                    // Wo @ query^T

// ---------------- tf32 mma helpers ----------------
__device__ __forceinline__ uint32_t f2tf32(float x) {
    uint32_t r;
    asm("cvt.rna.tf32.f32 %0, %1;" : "=r"(r) : "f"(x));
    return r;
}

__device__ __forceinline__ void mma_tf32(float* d,
                                         const uint32_t* a,
                                         const uint32_t* b)
{
    asm volatile(
        "mma.sync.aligned.m16n8k8.row.col.f32.tf32.tf32.f32 "
        "{%0,%1,%2,%3}, {%4,%5,%6,%7}, {%8,%9}, {%0,%1,%2,%3};\n"
        : "+f"(d[0]), "+f"(d[1]), "+f"(d[2]), "+f"(d[3])
        : "r"(a[0]), "r"(a[1]), "r"(a[2]), "r"(a[3]),
          "r"(b[0]), "r"(b[1]));
}

// ---------------- Kernel 1: QKV projection via tf32 tensor cores ----------------
// C[51200, 768] = A[51200,256] @ [Wq|Wk|Wv] + bias, scattered into [B,H,L,Dh].
// Block tile 64(M) x 128(N), k-chunk 16, double-buffered, 8 warps (2M x 4N),
// warp tile 32x32. Small register footprint -> 2+ CTAs/SM for latency hiding.
#define BK 16
#define STA 72    // A smem stride (64 + 8): frag bank (8c+g)%32, conflict-free
#define STB 136   // B smem stride (128 + 8): frag bank (8c+n)%32, conflict-free

__global__ __launch_bounds__(256)
void qkv_mma_kernel(const float* __restrict__ A,
                    const float* __restrict__ Wq, const float* __restrict__ bq,
                    const float* __restrict__ Wk, const float* __restrict__ bk,
                    const float* __restrict__ Wv, const float* __restrict__ bvec)
{
    __shared__ float As[2][BK][STA];   // transposed A tile [k][m], m<64
    __shared__ float Bs[2][BK][STB];   // B tile [k][n], n<128

    const int tid = threadIdx.x;
    const int bx  = blockIdx.x;          // 0..5 : N-slab of 128 within [Q|K|V]
    const int by  = blockIdx.y;          // 0..799 : M-slab of 64

    const int mat   = bx >> 1;           // 0=Q,1=K,2=V
    const int ncol0 = (bx & 1) * 128;    // 0 or 128 inside the 256-wide W

    const float* __restrict__ W    = (mat == 0) ? Wq : (mat == 1 ? Wk : Wv);
    const float* __restrict__ bias = (mat == 0) ? bq : (mat == 1 ? bk : bvec);
    float* OUT = (mat == 0) ? g_q : (mat == 1 ? g_k : g_v);

    const int lane = tid & 31;
    const int wid  = tid >> 5;
    const int warp_m = (wid & 1) * 32;   // 0 or 32
    const int warp_n = (wid >> 1) * 32;  // 0,32,64,96
    const int g = lane >> 2;             // row within 8
    const int c = lane & 3;              // k quarter

    // A loader: 64 rows x 16 k -> 4 elems/thread (1 float4), stored transposed
    const int am = tid & 63;
    const int ak = (tid >> 6) << 2;      // 0,4,8,12
    const float* Aptr = A + (size_t)(by * 64 + am) * ND + ak;

    // B loader: 16 k-rows x 128 n -> 8 elems/thread (2 float4), row-major
    const int bkr = tid >> 4;            // 0..15
    const int bn8 = (tid & 15) * 8;      // 0..120
    const float* Bptr = W + (size_t)bkr * ND + ncol0 + bn8;

    float4 pa, pb0, pb1;
    pa  = *(const float4*)(Aptr);
    pb0 = *(const float4*)(Bptr);
    pb1 = *(const float4*)(Bptr + 4);

    {
        As[0][ak + 0][am] = __uint_as_float(f2tf32(pa.x));
        As[0][ak + 1][am] = __uint_as_float(f2tf32(pa.y));
        As[0][ak + 2][am] = __uint_as_float(f2tf32(pa.z));
        As[0][ak + 3][am] = __uint_as_float(f2tf32(pa.w));
        float4 cb0 = make_float4(__uint_as_float(f2tf32(pb0.x)),
                                 __uint_as_float(f2tf32(pb0.y)),
                                 __uint_as_float(f2tf32(pb0.z)),
                                 __uint_as_float(f2tf32(pb0.w)));
        float4 cb1 = make_float4(__uint_as_float(f2tf32(pb1.x)),
                                 __uint_as_float(f2tf32(pb1.y)),
                                 __uint_as_float(f2tf32(pb1.z)),
                                 __uint_as_float(f2tf32(pb1.w)));
        *(float4*)&Bs[0][bkr][bn8]     = cb0;
        *(float4*)&Bs[0][bkr][bn8 + 4] = cb1;
    }
    __syncthreads();

    float acc[2][4][4];
    #pragma unroll
    for (int mi = 0; mi < 2; ++mi)
        #pragma unroll
        for (int nf = 0; nf < 4; ++nf)
            #pragma unroll
            for (int r = 0; r < 4; ++r) acc[mi][nf][r] = 0.f;

    #pragma unroll 1
    for (int ch = 0; ch < ND / BK; ++ch) {
        const int cur = ch & 1;
        if (ch < ND / BK - 1) {
            pa  = *(const float4*)(Aptr + (ch + 1) * BK);
            pb0 = *(const float4*)(Bptr + (size_t)(ch + 1) * BK * ND);
            pb1 = *(const float4*)(Bptr + (size_t)(ch + 1) * BK * ND + 4);
        }

        #pragma unroll
        for (int ks = 0; ks < 2; ++ks) {
            const int k0 = ks * 8;
            uint32_t afr[2][4];
            uint32_t bfr[4][2];
            #pragma unroll
            for (int mi = 0; mi < 2; ++mi) {
                const int m = warp_m + mi * 16 + g;
                afr[mi][0] = __float_as_uint(As[cur][k0 + c    ][m    ]);
                afr[mi][1] = __float_as_uint(As[cur][k0 + c    ][m + 8]);
                afr[mi][2] = __float_as_uint(As[cur][k0 + c + 4][m    ]);
                afr[mi][3] = __float_as_uint(As[cur][k0 + c + 4][m + 8]);
            }
            #pragma unroll
            for (int nf = 0; nf < 4; ++nf) {
                const int n = warp_n + nf * 8 + g;
                bfr[nf][0] = __float_as_uint(Bs[cur][k0 + c    ][n]);
                bfr[nf][1] = __float_as_uint(Bs[cur][k0 + c + 4][n]);
            }
            #pragma unroll
            for (int mi = 0; mi < 2; ++mi)
                #pragma unroll
                for (int nf = 0; nf < 4; ++nf)
                    mma_tf32(acc[mi][nf], afr[mi], bfr[nf]);
        }

        if (ch < ND / BK - 1) {
            const int nxt = cur ^ 1;
            As[nxt][ak + 0][am] = __uint_as_float(f2tf32(pa.x));
            As[nxt][ak + 1][am] = __uint_as_float(f2tf32(pa.y));
            As[nxt][ak + 2][am] = __uint_as_float(f2tf32(pa.z));
            As[nxt][ak + 3][am] = __uint_as_float(f2tf32(pa.w));
            float4 cb0 = make_float4(__uint_as_float(f2tf32(pb0.x)),
                                     __uint_as_float(f2tf32(pb0.y)),
                                     __uint_as_float(f2tf32(pb0.z)),
                                     __uint_as_float(f2tf32(pb0.w)));
            float4 cb1 = make_float4(__uint_as_float(f2tf32(pb1.x)),
                                     __uint_as_float(f2tf32(pb1.y)),
                                     __uint_as_float(f2tf32(pb1.z)),
                                     __uint_as_float(f2tf32(pb1.w)));
            *(float4*)&Bs[nxt][bkr][bn8]     = cb0;
            *(float4*)&Bs[nxt][bkr][bn8 + 4] = cb1;
            __syncthreads();
        }
    }

    // epilogue: +bias, scatter to [B,H,L,Dh]. Each warp covers 2 heads.
    const int h_base = (ncol0 >> 4) + (warp_n >> 4);
    #pragma unroll
    for (int mi = 0; mi < 2; ++mi) {
        const int r0 = by * 64 + warp_m + mi * 16 + g;
        const int r1 = r0 + 8;
        const int b0 = r0 / NL, l0 = r0 - b0 * NL;
        const int b1 = r1 / NL, l1 = r1 - b1 * NL;
        #pragma unroll
        for (int nf = 0; nf < 4; ++nf) {
            const int h = h_base + (nf >> 1);
            const int d = ((nf & 1) << 3) + 2 * c;      // even -> 8B aligned
            const float bi0 = bias[ncol0 + warp_n + nf * 8 + 2 * c];
            const float bi1 = bias[ncol0 + warp_n + nf * 8 + 2 * c + 1];
            float* p0 = OUT + (((size_t)(b0 * NH + h) * NL + l0) << 4) + d;
            float* p1 = OUT + (((size_t)(b1 * NH + h) * NL + l1) << 4) + d;
            *(float2*)p0 = make_float2(acc[mi][nf][0] + bi0, acc[mi][nf][1] + bi1);
            *(float2*)p1 = make_float2(acc[mi][nf][2] + bi0, acc[mi][nf][3] + bi1);
        }
    }
}

// ---------------- Kernel 2: tensor-core MHA per (b,h) ----------------
// S = Q K^T via mma (tf32), exp (no max: scores bounded, mask -> exact 0),
// P re-laid C-frag -> A-frag through warp-private smem staging, PV via mma.
#define VT_STRIDE 212
#define QK_STRIDE 17
#define PST_STRIDE 10   // EVEN stride: row base stays 8B-aligned for the float2 store

__global__ __launch_bounds__(256)
void attn_kernel(const int* __restrict__ his_mask)
{
    const int h = blockIdx.x;
    const int b = blockIdx.y;
    const int tid  = threadIdx.x;
    const int lane = tid & 31;
    const int wid  = tid >> 5;
    const int g = lane >> 2;     // row within 8
    const int c = lane & 3;      // quad col

    __shared__ float Qs[208][QK_STRIDE];        // tf32 bits, rows 200..207 zeroed
    __shared__ float Ks[200][QK_STRIDE];        // tf32 bits
    __shared__ float Vt[16][VT_STRIDE];         // transposed V, tf32 bits
    __shared__ float am[NL];
    __shared__ float Pst[8][16][PST_STRIDE];    // per-warp P staging (8B-aligned rows)

    const size_t base = (size_t)(b * NH + h) * NL * NDH;

    // loaders: 200 rows x 16, in float4 chunks
    for (int i = tid; i < NL * 4; i += 256) {
        const int row = i >> 2;
        const int d4  = (i & 3) << 2;
        float4 q = *(const float4*)(g_q + base + row * NDH + d4);
        float4 k = *(const float4*)(g_k + base + row * NDH + d4);
        float4 v = *(const float4*)(g_v + base + row * NDH + d4);
        Qs[row][d4 + 0] = __uint_as_float(f2tf32(q.x));
        Qs[row][d4 + 1] = __uint_as_float(f2tf32(q.y));
        Qs[row][d4 + 2] = __uint_as_float(f2tf32(q.z));
        Qs[row][d4 + 3] = __uint_as_float(f2tf32(q.w));
        Ks[row][d4 + 0] = __uint_as_float(f2tf32(k.x));
        Ks[row][d4 + 1] = __uint_as_float(f2tf32(k.y));
        Ks[row][d4 + 2] = __uint_as_float(f2tf32(k.z));
        Ks[row][d4 + 3] = __uint_as_float(f2tf32(k.w));
        Vt[d4 + 0][row] = __uint_as_float(f2tf32(v.x));
        Vt[d4 + 1][row] = __uint_as_float(f2tf32(v.y));
        Vt[d4 + 2][row] = __uint_as_float(f2tf32(v.z));
        Vt[d4 + 3][row] = __uint_as_float(f2tf32(v.w));
    }
    // zero Q pad rows (200..207)
    for (int i = tid; i < 8 * 16; i += 256)
        Qs[200 + (i >> 4)][i & 15] = 0.f;
    for (int i = tid; i < NL; i += 256)
        am[i] = (his_mask[b * NL + i] > 0) ? 0.f : -10000.f;
    __syncthreads();

    // 13 row-tiles of 16, round-robin over 8 warps
    for (int t = wid; t < 13; t += 8) {
        const int r0 = t * 16;

        // Q a-frags (persistent over key loop): 2 k-steps
        uint32_t aq[2][4];
        #pragma unroll
        for (int ks = 0; ks < 2; ++ks) {
            const int kk = ks * 8;
            aq[ks][0] = __float_as_uint(Qs[r0 + g    ][c     + kk]);
            aq[ks][1] = __float_as_uint(Qs[r0 + g + 8][c     + kk]);
            aq[ks][2] = __float_as_uint(Qs[r0 + g    ][c + 4 + kk]);
            aq[ks][3] = __float_as_uint(Qs[r0 + g + 8][c + 4 + kk]);
        }

        float ctx0[4] = {0.f, 0.f, 0.f, 0.f};   // dh 0..7
        float ctx1[4] = {0.f, 0.f, 0.f, 0.f};   // dh 8..15
        float sum_lo = 0.f, sum_hi = 0.f;

        #pragma unroll 1
        for (int kc = 0; kc < NL / 8; ++kc) {
            const int k0 = kc * 8;

            uint32_t bk0[2], bk1[2];
            bk0[0] = __float_as_uint(Ks[k0 + g][c     ]);
            bk0[1] = __float_as_uint(Ks[k0 + g][c + 4 ]);
            bk1[0] = __float_as_uint(Ks[k0 + g][c + 8 ]);
            bk1[1] = __float_as_uint(Ks[k0 + g][c + 12]);

            float s[4] = {0.f, 0.f, 0.f, 0.f};
            mma_tf32(s, aq[0], bk0);
            mma_tf32(s, aq[1], bk1);

            const float a0 = am[k0 + 2 * c];
            const float a1 = am[k0 + 2 * c + 1];
            float p0 = __expf(fmaf(s[0], 0.25f, a0));
            float p1 = __expf(fmaf(s[1], 0.25f, a1));
            float p2 = __expf(fmaf(s[2], 0.25f, a0));
            float p3 = __expf(fmaf(s[3], 0.25f, a1));

            // round P to tf32 ONCE; use same values for numerator and denominator
            const uint32_t t0 = f2tf32(p0), t1 = f2tf32(p1);
            const uint32_t t2 = f2tf32(p2), t3 = f2tf32(p3);
            const float q0 = __uint_as_float(t0), q1 = __uint_as_float(t1);
            const float q2 = __uint_as_float(t2), q3 = __uint_as_float(t3);
            sum_lo += q0 + q1;
            sum_hi += q2 + q3;

            // stage C-frag -> A-frag layout (rows are 40B apart: float2 stays aligned)
            *(float2*)&Pst[wid][g    ][2 * c] = make_float2(q0, q1);
            *(float2*)&Pst[wid][g + 8][2 * c] = make_float2(q2, q3);
            __syncwarp();

            uint32_t ap[4];
            ap[0] = __float_as_uint(Pst[wid][g    ][c    ]);
            ap[1] = __float_as_uint(Pst[wid][g + 8][c    ]);
            ap[2] = __float_as_uint(Pst[wid][g    ][c + 4]);
            ap[3] = __float_as_uint(Pst[wid][g + 8][c + 4]);

            uint32_t bv0[2], bv1[2];
            bv0[0] = __float_as_uint(Vt[g    ][k0 + c    ]);
            bv0[1] = __float_as_uint(Vt[g    ][k0 + c + 4]);
            bv1[0] = __float_as_uint(Vt[g + 8][k0 + c    ]);
            bv1[1] = __float_as_uint(Vt[g + 8][k0 + c + 4]);

            mma_tf32(ctx0, ap, bv0);
            mma_tf32(ctx1, ap, bv1);
            __syncwarp();
        }

        // row sums: reduce across the 4 quad threads
        sum_lo += __shfl_xor_sync(0xffffffffu, sum_lo, 1);
        sum_lo += __shfl_xor_sync(0xffffffffu, sum_lo, 2);
        sum_hi += __shfl_xor_sync(0xffffffffu, sum_hi, 1);
        sum_hi += __shfl_xor_sync(0xffffffffu, sum_hi, 2);
        const float inv_lo = 1.0f / sum_lo;
        const float inv_hi = 1.0f / sum_hi;

        const int row_lo = r0 + g;
        const int row_hi = r0 + g + 8;
        if (row_lo < NL) {
            float* p = g_ctx + ((size_t)b * NL + row_lo) * ND + h * NDH;
            *(float2*)(p + 2 * c)     = make_float2(ctx0[0] * inv_lo, ctx0[1] * inv_lo);
            *(float2*)(p + 8 + 2 * c) = make_float2(ctx1[0] * inv_lo, ctx1[1] * inv_lo);
        }
        if (row_hi < NL) {
            float* p = g_ctx + ((size_t)b * NL + row_hi) * ND + h * NDH;
            *(float2*)(p + 2 * c)     = make_float2(ctx0[2] * inv_hi, ctx0[3] * inv_hi);
            *(float2*)(p + 8 + 2 * c) = make_float2(ctx1[2] * inv_hi, ctx1[3] * inv_hi);
        }
    }
}

// ---------------- Kernel 3a: u = Wo @ query^T  (tiny) ----------------
__global__ __launch_bounds__(256)
void u_kernel(const float* __restrict__ Wo, const float* __restrict__ query)
{
    __shared__ float qs[ND];
    const int tid = threadIdx.x;
    qs[tid] = query[tid];
    __syncthreads();
    const float* row = Wo + (size_t)tid * ND;
    float a0 = 0.f, a1 = 0.f, a2 = 0.f, a3 = 0.f;
    #pragma unroll 8
    for (int n = 0; n < ND; n += 4) {
        a0 = fmaf(row[n + 0], qs[n + 0], a0);
        a1 = fmaf(row[n + 1], qs[n + 1], a1);
        a2 = fmaf(row[n + 2], qs[n + 2], a2);
        a3 = fmaf(row[n + 3], qs[n + 3], a3);
    }
    g_u[tid] = (a0 + a1) + (a2 + a3);
}

// ---------------- Kernel 3b: masked softmax pooling + projected epilogue ----------
__global__ __launch_bounds__(256)
void pool_kernel(const float* __restrict__ Wo, const float* __restrict__ bo,
                 const int* __restrict__ his_mask, float* __restrict__ out)
{
    const int b    = blockIdx.x;
    const int tid  = threadIdx.x;
    const int lane = tid & 31;
    const int warp = tid >> 5;

    __shared__ float ps[NL];
    __shared__ float pooled[ND];
    __shared__ float red[8];

    const float* C = g_ctx + (size_t)b * NL * ND;

    float4 ua = ((const float4*)g_u)[lane * 2];
    float4 ub = ((const float4*)g_u)[lane * 2 + 1];

    for (int l = warp; l < NL; l += 8) {
        const float4* c4 = (const float4*)(C + (size_t)l * ND);
        float4 xa = c4[lane * 2], xb = c4[lane * 2 + 1];
        float acc = xa.x * ua.x + xa.y * ua.y + xa.z * ua.z + xa.w * ua.w
                  + xb.x * ub.x + xb.y * ub.y + xb.z * ub.z + xb.w * ub.w;
        #pragma unroll
        for (int o = 16; o; o >>= 1) acc += __shfl_xor_sync(0xffffffffu, acc, o);
        if (lane == 0)
            ps[l] = (his_mask[b * NL + l] > 0) ? acc * 0.0625f : -1e9f;
    }
    __syncthreads();

    float v = (tid < NL) ? ps[tid] : -3.0e38f;
    float mx = v;
    #pragma unroll
    for (int o = 16; o; o >>= 1) mx = fmaxf(mx, __shfl_xor_sync(0xffffffffu, mx, o));
    if (lane == 0) red[warp] = mx;
    __syncthreads();
    float bm = red[0];
    #pragma unroll
    for (int i = 1; i < 8; ++i) bm = fmaxf(bm, red[i]);

    float e = (tid < NL) ? __expf(v - bm) : 0.f;
    float sv = e;
    #pragma unroll
    for (int o = 16; o; o >>= 1) sv += __shfl_xor_sync(0xffffffffu, sv, o);
    __syncthreads();
    if (lane == 0) red[warp] = sv;
    if (tid < NL) ps[tid] = e;
    __syncthreads();
    float tot = (red[0] + red[1]) + (red[2] + red[3])
              + (red[4] + red[5]) + (red[6] + red[7]);
    float inv = 1.0f / tot;

    {
        float a0 = 0.f, a1 = 0.f, a2 = 0.f, a3 = 0.f;
        const float* Cd = C + tid;
        for (int l = 0; l < NL; l += 4) {
            a0 = fmaf(ps[l + 0], Cd[(size_t)(l + 0) * ND], a0);
            a1 = fmaf(ps[l + 1], Cd[(size_t)(l + 1) * ND], a1);
            a2 = fmaf(ps[l + 2], Cd[(size_t)(l + 2) * ND], a2);
            a3 = fmaf(ps[l + 3], Cd[(size_t)(l + 3) * ND], a3);
        }
        pooled[tid] = ((a0 + a1) + (a2 + a3)) * inv;
    }
    __syncthreads();

    float o = bo[tid];
    const float* Wn = Wo + tid;
    #pragma unroll 8
    for (int d = 0; d < ND; ++d) o = fmaf(pooled[d], Wn[(size_t)d * ND], o);
    out[(size_t)b * ND + tid] = o;
}

// ---------------- launch ----------------
extern "C" void kernel_launch(void* const* d_in, const int* in_sizes, int n_in,
                              void* d_out, int out_size)
{
    const float* news  = (const float*)d_in[0];
    const int*   hmask = (const int*)  d_in[1];
    const float* Wq    = (const float*)d_in[2];
    const float* bq    = (const float*)d_in[3];
    const float* Wk    = (const float*)d_in[4];
    const float* bk    = (const float*)d_in[5];
    const float* Wv    = (const float*)d_in[6];
    const float* bvv   = (const float*)d_in[7];
    const float* Wo    = (const float*)d_in[8];
    const float* bo    = (const float*)d_in[9];
    const float* query = (const float*)d_in[10];
    float* out = (float*)d_out;

    dim3 gemm_grid(6, (NB * NL) / 64);             // 6 x 800
    qkv_mma_kernel<<<gemm_grid, 256>>>(news, Wq, bq, Wk, bk, Wv, bvv);

    dim3 attn_grid(NH, NB);                        // 16 x 256
    attn_kernel<<<attn_grid, 256>>>(hmask);

    u_kernel<<<1, 256>>>(Wo, query);

    pool_kernel<<<NB, 256>>>(Wo, bo, hmask, out);
}

// round 13
// speedup vs baseline: 1.4175x; 1.4175x over previous
#include <cuda_runtime.h>
#include <cuda_fp16.h>
#include <cstdint>

#define NB   256   // batch
#define NL   200   // seq len
#define ND   256   // model dim
#define NH   16    // heads
#define NDH  16    // head dim

// ---------------- scratch (device globals: alloc-free) ----------------
__device__ __half g_q[NB * NH * NL * NDH];   // [B,H,L,Dh] fp16
__device__ __half g_k[NB * NH * NL * NDH];
__device__ __half g_v[NB * NH * NL * NDH];
__device__ float  g_ctx[NB * NL * ND];       // [B,L,D] fp32
__device__ float  g_u[ND];                   // Wo @ query^T

// ---------------- fp16 mma helpers ----------------
__device__ __forceinline__ uint32_t pack_h2(float a, float b) {
    __half2 h = __floats2half2_rn(a, b);
    return *(uint32_t*)&h;
}

__device__ __forceinline__ void mma_f16_16816(float* d,
                                              const uint32_t* a,
                                              const uint32_t* b)
{
    asm volatile(
        "mma.sync.aligned.m16n8k16.row.col.f32.f16.f16.f32 "
        "{%0,%1,%2,%3}, {%4,%5,%6,%7}, {%8,%9}, {%0,%1,%2,%3};\n"
        : "+f"(d[0]), "+f"(d[1]), "+f"(d[2]), "+f"(d[3])
        : "r"(a[0]), "r"(a[1]), "r"(a[2]), "r"(a[3]),
          "r"(b[0]), "r"(b[1]));
}

__device__ __forceinline__ void mma_f16_1688(float* d,
                                             uint32_t a0, uint32_t a1,
                                             uint32_t b0)
{
    asm volatile(
        "mma.sync.aligned.m16n8k8.row.col.f32.f16.f16.f32 "
        "{%0,%1,%2,%3}, {%4,%5}, {%6}, {%0,%1,%2,%3};\n"
        : "+f"(d[0]), "+f"(d[1]), "+f"(d[2]), "+f"(d[3])
        : "r"(a0), "r"(a1), "r"(b0));
}

// ---------------- Kernel 1: QKV projection via fp16 tensor cores ----------------
// C[51200, 768] = A[51200,256] @ [Wq|Wk|Wv] + bias -> fp16 scatter to [B,H,L,Dh].
// Block tile 128(M) x 128(N), k-chunk 16, double-buffered, 8 warps (2M x 4N),
// warp tile 64x32, m16n8k16. Smem tiles in half: A row-major [m][k], B [n][k].
#define BK 16
#define QST 24   // half-stride (12 words): frag banks (12g+c) = full bijection mod 32

__global__ __launch_bounds__(256, 2)
void qkv_mma_kernel(const float* __restrict__ A,
                    const float* __restrict__ Wq, const float* __restrict__ bq,
                    const float* __restrict__ Wk, const float* __restrict__ bk,
                    const float* __restrict__ Wv, const float* __restrict__ bvec)
{
    __shared__ __half As[2][128][QST];   // [m][k] row-major
    __shared__ __half Bs[2][128][QST];   // [n][k] (transposed W)

    const int tid = threadIdx.x;
    const int bx  = blockIdx.x;          // 0..5 : N-slab of 128 within [Q|K|V]
    const int by  = blockIdx.y;          // 0..399

    const int mat   = bx >> 1;           // 0=Q,1=K,2=V
    const int ncol0 = (bx & 1) * 128;

    const float* __restrict__ W    = (mat == 0) ? Wq : (mat == 1 ? Wk : Wv);
    const float* __restrict__ bias = (mat == 0) ? bq : (mat == 1 ? bk : bvec);
    __half* OUT = (mat == 0) ? g_q : (mat == 1 ? g_k : g_v);

    const int lane = tid & 31;
    const int wid  = tid >> 5;
    const int warp_m = (wid & 1) * 64;   // 0 or 64
    const int warp_n = (wid >> 1) * 32;  // 0,32,64,96
    const int g = lane >> 2;             // row within 8
    const int c = lane & 3;              // quad col

    // A loader: 128 rows x 16 k -> 8 floats/thread (2 float4), row-major halves
    const int am = tid & 127;
    const int ak = (tid >> 7) * 8;       // 0 or 8
    const float* Aptr = A + (size_t)(by * 128 + am) * ND + ak;

    // B loader: 16 k-rows x 128 n -> 8 floats/thread (2 float4), transposed store
    const int bkr = tid >> 4;            // 0..15 (k row)
    const int bn4 = (tid & 15) * 4;      // n offset; second group at +64
    const float* Bptr = W + (size_t)bkr * ND + ncol0 + bn4;

    float4 pa0, pa1, pb0, pb1;
    pa0 = *(const float4*)(Aptr);
    pa1 = *(const float4*)(Aptr + 4);
    pb0 = *(const float4*)(Bptr);
    pb1 = *(const float4*)(Bptr + 64);

    {
        uint2 ha;
        ha.x = pack_h2(pa0.x, pa0.y);  ha.y = pack_h2(pa0.z, pa0.w);
        *(uint2*)&As[0][am][ak] = ha;
        ha.x = pack_h2(pa1.x, pa1.y);  ha.y = pack_h2(pa1.z, pa1.w);
        *(uint2*)&As[0][am][ak + 4] = ha;
        Bs[0][bn4 + 0][bkr] = __float2half_rn(pb0.x);
        Bs[0][bn4 + 1][bkr] = __float2half_rn(pb0.y);
        Bs[0][bn4 + 2][bkr] = __float2half_rn(pb0.z);
        Bs[0][bn4 + 3][bkr] = __float2half_rn(pb0.w);
        Bs[0][bn4 + 64][bkr] = __float2half_rn(pb1.x);
        Bs[0][bn4 + 65][bkr] = __float2half_rn(pb1.y);
        Bs[0][bn4 + 66][bkr] = __float2half_rn(pb1.z);
        Bs[0][bn4 + 67][bkr] = __float2half_rn(pb1.w);
    }
    __syncthreads();

    float acc[4][4][4];
    #pragma unroll
    for (int mi = 0; mi < 4; ++mi)
        #pragma unroll
        for (int nf = 0; nf < 4; ++nf)
            #pragma unroll
            for (int r = 0; r < 4; ++r) acc[mi][nf][r] = 0.f;

    #pragma unroll 1
    for (int ch = 0; ch < ND / BK; ++ch) {
        const int cur = ch & 1;
        if (ch < ND / BK - 1) {
            pa0 = *(const float4*)(Aptr + (ch + 1) * BK);
            pa1 = *(const float4*)(Aptr + (ch + 1) * BK + 4);
            pb0 = *(const float4*)(Bptr + (size_t)(ch + 1) * BK * ND);
            pb1 = *(const float4*)(Bptr + (size_t)(ch + 1) * BK * ND + 64);
        }

        // fragments: one m16n8k16 k-step per chunk
        uint32_t afr[4][4];
        uint32_t bfr[4][2];
        #pragma unroll
        for (int mi = 0; mi < 4; ++mi) {
            const int m = warp_m + mi * 16 + g;
            afr[mi][0] = *(const uint32_t*)&As[cur][m    ][2 * c    ];
            afr[mi][1] = *(const uint32_t*)&As[cur][m + 8][2 * c    ];
            afr[mi][2] = *(const uint32_t*)&As[cur][m    ][2 * c + 8];
            afr[mi][3] = *(const uint32_t*)&As[cur][m + 8][2 * c + 8];
        }
        #pragma unroll
        for (int nf = 0; nf < 4; ++nf) {
            const int n = warp_n + nf * 8 + g;
            bfr[nf][0] = *(const uint32_t*)&Bs[cur][n][2 * c    ];
            bfr[nf][1] = *(const uint32_t*)&Bs[cur][n][2 * c + 8];
        }
        #pragma unroll
        for (int mi = 0; mi < 4; ++mi)
            #pragma unroll
            for (int nf = 0; nf < 4; ++nf)
                mma_f16_16816(acc[mi][nf], afr[mi], bfr[nf]);

        if (ch < ND / BK - 1) {
            const int nxt = cur ^ 1;
            uint2 ha;
            ha.x = pack_h2(pa0.x, pa0.y);  ha.y = pack_h2(pa0.z, pa0.w);
            *(uint2*)&As[nxt][am][ak] = ha;
            ha.x = pack_h2(pa1.x, pa1.y);  ha.y = pack_h2(pa1.z, pa1.w);
            *(uint2*)&As[nxt][am][ak + 4] = ha;
            Bs[nxt][bn4 + 0][bkr] = __float2half_rn(pb0.x);
            Bs[nxt][bn4 + 1][bkr] = __float2half_rn(pb0.y);
            Bs[nxt][bn4 + 2][bkr] = __float2half_rn(pb0.z);
            Bs[nxt][bn4 + 3][bkr] = __float2half_rn(pb0.w);
            Bs[nxt][bn4 + 64][bkr] = __float2half_rn(pb1.x);
            Bs[nxt][bn4 + 65][bkr] = __float2half_rn(pb1.y);
            Bs[nxt][bn4 + 66][bkr] = __float2half_rn(pb1.z);
            Bs[nxt][bn4 + 67][bkr] = __float2half_rn(pb1.w);
            __syncthreads();
        }
    }

    // epilogue: +bias (fp32), round to fp16, scatter to [B,H,L,Dh]
    const int h_base = (ncol0 >> 4) + (warp_n >> 4);
    #pragma unroll
    for (int mi = 0; mi < 4; ++mi) {
        const int r0 = by * 128 + warp_m + mi * 16 + g;
        const int r1 = r0 + 8;
        const int b0 = r0 / NL, l0 = r0 - b0 * NL;
        const int b1 = r1 / NL, l1 = r1 - b1 * NL;
        #pragma unroll
        for (int nf = 0; nf < 4; ++nf) {
            const int h = h_base + (nf >> 1);
            const int d = ((nf & 1) << 3) + 2 * c;       // even -> 4B aligned
            const float bi0 = bias[ncol0 + warp_n + nf * 8 + 2 * c];
            const float bi1 = bias[ncol0 + warp_n + nf * 8 + 2 * c + 1];
            __half* p0 = OUT + (((size_t)(b0 * NH + h) * NL + l0) << 4) + d;
            __half* p1 = OUT + (((size_t)(b1 * NH + h) * NL + l1) << 4) + d;
            uint32_t v0 = pack_h2(acc[mi][nf][0] + bi0, acc[mi][nf][1] + bi1);
            uint32_t v1 = pack_h2(acc[mi][nf][2] + bi0, acc[mi][nf][3] + bi1);
            *(uint32_t*)p0 = v0;
            *(uint32_t*)p1 = v1;
        }
    }
}

// ---------------- Kernel 2: fp16 tensor-core MHA per (b,h) ----------------
// S = Q K^T (m16n8k16). exp (no max: scores bounded; masked -> exact 0).
// S C-frag rounds to half2 -> IS the m16n8k8 A-frag for PV: zero staging.
#define AKST 24    // Q/K half-stride (12 words -> conflict-free bijection)
#define VTST 216   // Vt half-stride (108 words, 108%32==12 -> same bijection)

__global__ __launch_bounds__(256)
void attn_kernel(const int* __restrict__ his_mask)
{
    const int h = blockIdx.x;
    const int b = blockIdx.y;
    const int tid  = threadIdx.x;
    const int lane = tid & 31;
    const int wid  = tid >> 5;
    const int g = lane >> 2;     // row within 8
    const int c = lane & 3;      // quad col

    __shared__ __half Qs[208][AKST];     // rows 200..207 zeroed
    __shared__ __half Ks[200][AKST];
    __shared__ __half Vt[16][VTST];      // transposed V: [dh][key]
    __shared__ float  am[NL];

    const size_t base = (size_t)(b * NH + h) * NL * NDH;

    // Q/K: straight fp16 copy, 16B chunks
    for (int i = tid; i < NL * 2; i += 256) {
        const int row = i >> 1;
        const int p8  = (i & 1) * 8;
        *(uint4*)&Qs[row][p8] = *(const uint4*)(g_q + base + row * NDH + p8);
        *(uint4*)&Ks[row][p8] = *(const uint4*)(g_k + base + row * NDH + p8);
    }
    // V transpose: one row per thread
    for (int row = tid; row < NL; row += 256) {
        const uint4* vp = (const uint4*)(g_v + base + row * NDH);
        uint4 v0 = vp[0], v1 = vp[1];
        __half hbuf[16];
        *(uint4*)&hbuf[0] = v0;
        *(uint4*)&hbuf[8] = v1;
        #pragma unroll
        for (int d = 0; d < 16; ++d) Vt[d][row] = hbuf[d];
    }
    // zero Q pad rows (200..207)
    if (tid < 16) {
        const int row = 200 + (tid >> 1);
        const int p8  = (tid & 1) * 8;
        *(uint4*)&Qs[row][p8] = make_uint4(0, 0, 0, 0);
    }
    for (int i = tid; i < NL; i += 256)
        am[i] = (his_mask[b * NL + i] > 0) ? 0.f : -10000.f;
    __syncthreads();

    // 13 row-tiles of 16, round-robin over 8 warps
    for (int t = wid; t < 13; t += 8) {
        const int r0 = t * 16;

        uint32_t aq[4];
        aq[0] = *(const uint32_t*)&Qs[r0 + g    ][2 * c    ];
        aq[1] = *(const uint32_t*)&Qs[r0 + g + 8][2 * c    ];
        aq[2] = *(const uint32_t*)&Qs[r0 + g    ][2 * c + 8];
        aq[3] = *(const uint32_t*)&Qs[r0 + g + 8][2 * c + 8];

        float ctx0[4] = {0.f, 0.f, 0.f, 0.f};   // dh 0..7
        float ctx1[4] = {0.f, 0.f, 0.f, 0.f};   // dh 8..15
        float sum_lo = 0.f, sum_hi = 0.f;

        for (int kc = 0; kc < NL / 8; ++kc) {
            const int k0 = kc * 8;

            uint32_t bk[2];
            bk[0] = *(const uint32_t*)&Ks[k0 + g][2 * c    ];
            bk[1] = *(const uint32_t*)&Ks[k0 + g][2 * c + 8];

            float s[4] = {0.f, 0.f, 0.f, 0.f};
            mma_f16_16816(s, aq, bk);

            const float a0 = am[k0 + 2 * c];
            const float a1 = am[k0 + 2 * c + 1];
            float p0 = __expf(fmaf(s[0], 0.25f, a0));
            float p1 = __expf(fmaf(s[1], 0.25f, a1));
            float p2 = __expf(fmaf(s[2], 0.25f, a0));
            float p3 = __expf(fmaf(s[3], 0.25f, a1));

            // round to fp16 ONCE; identical values feed numerator and denominator
            const uint32_t plo = pack_h2(p0, p1);   // A-frag a0 (row g)
            const uint32_t phi = pack_h2(p2, p3);   // A-frag a1 (row g+8)
            float2 flo = __half22float2(*(const __half2*)&plo);
            float2 fhi = __half22float2(*(const __half2*)&phi);
            sum_lo += flo.x + flo.y;
            sum_hi += fhi.x + fhi.y;

            const uint32_t bv0 = *(const uint32_t*)&Vt[g    ][k0 + 2 * c];
            const uint32_t bv1 = *(const uint32_t*)&Vt[g + 8][k0 + 2 * c];
            mma_f16_1688(ctx0, plo, phi, bv0);
            mma_f16_1688(ctx1, plo, phi, bv1);
        }

        sum_lo += __shfl_xor_sync(0xffffffffu, sum_lo, 1);
        sum_lo += __shfl_xor_sync(0xffffffffu, sum_lo, 2);
        sum_hi += __shfl_xor_sync(0xffffffffu, sum_hi, 1);
        sum_hi += __shfl_xor_sync(0xffffffffu, sum_hi, 2);
        const float inv_lo = 1.0f / sum_lo;
        const float inv_hi = 1.0f / sum_hi;

        const int row_lo = r0 + g;
        const int row_hi = r0 + g + 8;
        if (row_lo < NL) {
            float* p = g_ctx + ((size_t)b * NL + row_lo) * ND + h * NDH;
            *(float2*)(p + 2 * c)     = make_float2(ctx0[0] * inv_lo, ctx0[1] * inv_lo);
            *(float2*)(p + 8 + 2 * c) = make_float2(ctx1[0] * inv_lo, ctx1[1] * inv_lo);
        }
        if (row_hi < NL) {
            float* p = g_ctx + ((size_t)b * NL + row_hi) * ND + h * NDH;
            *(float2*)(p + 2 * c)     = make_float2(ctx0[2] * inv_hi, ctx0[3] * inv_hi);
            *(float2*)(p + 8 + 2 * c) = make_float2(ctx1[2] * inv_hi, ctx1[3] * inv_hi);
        }
    }
}

// ---------------- Kernel 3a: u = Wo @ query^T  (tiny) ----------------
__global__ __launch_bounds__(256)
void u_kernel(const float* __restrict__ Wo, const float* __restrict__ query)
{
    __shared__ float qs[ND];
    const int tid = threadIdx.x;
    qs[tid] = query[tid];
    __syncthreads();
    const float* row = Wo + (size_t)tid * ND;
    float a0 = 0.f, a1 = 0.f, a2 = 0.f, a3 = 0.f;
    #pragma unroll 8
    for (int n = 0; n < ND; n += 4) {
        a0 = fmaf(row[n + 0], qs[n + 0], a0);
        a1 = fmaf(row[n + 1], qs[n + 1], a1);
        a2 = fmaf(row[n + 2], qs[n + 2], a2);
        a3 = fmaf(row[n + 3], qs[n + 3], a3);
    }
    g_u[tid] = (a0 + a1) + (a2 + a3);
}

// ---------------- Kernel 3b: masked softmax pooling + projected epilogue ----------
__global__ __launch_bounds__(256)
void pool_kernel(const float* __restrict__ Wo, const float* __restrict__ bo,
                 const int* __restrict__ his_mask, float* __restrict__ out)
{
    const int b    = blockIdx.x;
    const int tid  = threadIdx.x;
    const int lane = tid & 31;
    const int warp = tid >> 5;

    __shared__ float ps[NL];
    __shared__ float pooled[ND];
    __shared__ float red[8];

    const float* C = g_ctx + (size_t)b * NL * ND;

    float4 ua = ((const float4*)g_u)[lane * 2];
    float4 ub = ((const float4*)g_u)[lane * 2 + 1];

    for (int l = warp; l < NL; l += 8) {
        const float4* c4 = (const float4*)(C + (size_t)l * ND);
        float4 xa = c4[lane * 2], xb = c4[lane * 2 + 1];
        float acc = xa.x * ua.x + xa.y * ua.y + xa.z * ua.z + xa.w * ua.w
                  + xb.x * ub.x + xb.y * ub.y + xb.z * ub.z + xb.w * ub.w;
        #pragma unroll
        for (int o = 16; o; o >>= 1) acc += __shfl_xor_sync(0xffffffffu, acc, o);
        if (lane == 0)
            ps[l] = (his_mask[b * NL + l] > 0) ? acc * 0.0625f : -1e9f;
    }
    __syncthreads();

    float v = (tid < NL) ? ps[tid] : -3.0e38f;
    float mx = v;
    #pragma unroll
    for (int o = 16; o; o >>= 1) mx = fmaxf(mx, __shfl_xor_sync(0xffffffffu, mx, o));
    if (lane == 0) red[warp] = mx;
    __syncthreads();
    float bm = red[0];
    #pragma unroll
    for (int i = 1; i < 8; ++i) bm = fmaxf(bm, red[i]);

    float e = (tid < NL) ? __expf(v - bm) : 0.f;
    float sv = e;
    #pragma unroll
    for (int o = 16; o; o >>= 1) sv += __shfl_xor_sync(0xffffffffu, sv, o);
    __syncthreads();
    if (lane == 0) red[warp] = sv;
    if (tid < NL) ps[tid] = e;
    __syncthreads();
    float tot = (red[0] + red[1]) + (red[2] + red[3])
              + (red[4] + red[5]) + (red[6] + red[7]);
    float inv = 1.0f / tot;

    {
        float a0 = 0.f, a1 = 0.f, a2 = 0.f, a3 = 0.f;
        const float* Cd = C + tid;
        for (int l = 0; l < NL; l += 4) {
            a0 = fmaf(ps[l + 0], Cd[(size_t)(l + 0) * ND], a0);
            a1 = fmaf(ps[l + 1], Cd[(size_t)(l + 1) * ND], a1);
            a2 = fmaf(ps[l + 2], Cd[(size_t)(l + 2) * ND], a2);
            a3 = fmaf(ps[l + 3], Cd[(size_t)(l + 3) * ND], a3);
        }
        pooled[tid] = ((a0 + a1) + (a2 + a3)) * inv;
    }
    __syncthreads();

    float o = bo[tid];
    const float* Wn = Wo + tid;
    #pragma unroll 8
    for (int d = 0; d < ND; ++d) o = fmaf(pooled[d], Wn[(size_t)d * ND], o);
    out[(size_t)b * ND + tid] = o;
}

// ---------------- launch ----------------
extern "C" void kernel_launch(void* const* d_in, const int* in_sizes, int n_in,
                              void* d_out, int out_size)
{
    const float* news  = (const float*)d_in[0];
    const int*   hmask = (const int*)  d_in[1];
    const float* Wq    = (const float*)d_in[2];
    const float* bq    = (const float*)d_in[3];
    const float* Wk    = (const float*)d_in[4];
    const float* bk    = (const float*)d_in[5];
    const float* Wv    = (const float*)d_in[6];
    const float* bvv   = (const float*)d_in[7];
    const float* Wo    = (const float*)d_in[8];
    const float* bo    = (const float*)d_in[9];
    const float* query = (const float*)d_in[10];
    float* out = (float*)d_out;

    dim3 gemm_grid(6, (NB * NL) / 128);            // 6 x 400
    qkv_mma_kernel<<<gemm_grid, 256>>>(news, Wq, bq, Wk, bk, Wv, bvv);

    dim3 attn_grid(NH, NB);                        // 16 x 256
    attn_kernel<<<attn_grid, 256>>>(hmask);

    u_kernel<<<1, 256>>>(Wo, query);

    pool_kernel<<<NB, 256>>>(Wo, bo, hmask, out);
}

// round 14
// speedup vs baseline: 1.4209x; 1.0024x over previous
#include <cuda_runtime.h>
#include <cuda_fp16.h>
#include <cstdint>

#define NB   256   // batch
#define NL   200   // seq len
#define ND   256   // model dim
#define NH   16    // heads
#define NDH  16    // head dim

// ---------------- scratch (device globals: alloc-free) ----------------
__device__ __half g_q[NB * NH * NL * NDH];   // [B,H,L,Dh] fp16
__device__ __half g_k[NB * NH * NL * NDH];
__device__ __half g_v[NB * NH * NL * NDH];
__device__ __half g_ctx[NB * NL * ND];       // [B,L,D] fp16
__device__ float  g_u[ND];                   // Wo @ query^T (fp32)

// ---------------- fp16 mma helpers ----------------
__device__ __forceinline__ uint32_t pack_h2(float a, float b) {
    __half2 h = __floats2half2_rn(a, b);
    return *(uint32_t*)&h;
}

__device__ __forceinline__ void mma_f16_16816(float* d,
                                              const uint32_t* a,
                                              const uint32_t* b)
{
    asm volatile(
        "mma.sync.aligned.m16n8k16.row.col.f32.f16.f16.f32 "
        "{%0,%1,%2,%3}, {%4,%5,%6,%7}, {%8,%9}, {%0,%1,%2,%3};\n"
        : "+f"(d[0]), "+f"(d[1]), "+f"(d[2]), "+f"(d[3])
        : "r"(a[0]), "r"(a[1]), "r"(a[2]), "r"(a[3]),
          "r"(b[0]), "r"(b[1]));
}

__device__ __forceinline__ void mma_f16_1688(float* d,
                                             uint32_t a0, uint32_t a1,
                                             uint32_t b0)
{
    asm volatile(
        "mma.sync.aligned.m16n8k8.row.col.f32.f16.f16.f32 "
        "{%0,%1,%2,%3}, {%4,%5}, {%6}, {%0,%1,%2,%3};\n"
        : "+f"(d[0]), "+f"(d[1]), "+f"(d[2]), "+f"(d[3])
        : "r"(a0), "r"(a1), "r"(b0));
}

// ---------------- Kernel 1: QKV projection via fp16 tensor cores ----------------
// C[51200, 768] = A[51200,256] @ [Wq|Wk|Wv] + bias -> fp16 scatter to [B,H,L,Dh].
// Block tile 128(M) x 128(N), k-chunk 16, double-buffered, 8 warps (2M x 4N),
// warp tile 64x32, m16n8k16.
#define BK 16
#define QST 24   // half-stride (12 words): frag banks (12g+c) = full bijection mod 32

__global__ __launch_bounds__(256, 2)
void qkv_mma_kernel(const float* __restrict__ A,
                    const float* __restrict__ Wq, const float* __restrict__ bq,
                    const float* __restrict__ Wk, const float* __restrict__ bk,
                    const float* __restrict__ Wv, const float* __restrict__ bvec)
{
    __shared__ __half As[2][128][QST];   // [m][k] row-major
    __shared__ __half Bs[2][128][QST];   // [n][k] (transposed W)

    const int tid = threadIdx.x;
    const int bx  = blockIdx.x;          // 0..5 : N-slab of 128 within [Q|K|V]
    const int by  = blockIdx.y;          // 0..399

    const int mat   = bx >> 1;           // 0=Q,1=K,2=V
    const int ncol0 = (bx & 1) * 128;

    const float* __restrict__ W    = (mat == 0) ? Wq : (mat == 1 ? Wk : Wv);
    const float* __restrict__ bias = (mat == 0) ? bq : (mat == 1 ? bk : bvec);
    __half* OUT = (mat == 0) ? g_q : (mat == 1 ? g_k : g_v);

    const int lane = tid & 31;
    const int wid  = tid >> 5;
    const int warp_m = (wid & 1) * 64;   // 0 or 64
    const int warp_n = (wid >> 1) * 32;  // 0,32,64,96
    const int g = lane >> 2;             // row within 8
    const int c = lane & 3;              // quad col

    const int am = tid & 127;
    const int ak = (tid >> 7) * 8;       // 0 or 8
    const float* Aptr = A + (size_t)(by * 128 + am) * ND + ak;

    const int bkr = tid >> 4;            // 0..15 (k row)
    const int bn4 = (tid & 15) * 4;      // n offset; second group at +64
    const float* Bptr = W + (size_t)bkr * ND + ncol0 + bn4;

    float4 pa0, pa1, pb0, pb1;
    pa0 = *(const float4*)(Aptr);
    pa1 = *(const float4*)(Aptr + 4);
    pb0 = *(const float4*)(Bptr);
    pb1 = *(const float4*)(Bptr + 64);

    {
        uint2 ha;
        ha.x = pack_h2(pa0.x, pa0.y);  ha.y = pack_h2(pa0.z, pa0.w);
        *(uint2*)&As[0][am][ak] = ha;
        ha.x = pack_h2(pa1.x, pa1.y);  ha.y = pack_h2(pa1.z, pa1.w);
        *(uint2*)&As[0][am][ak + 4] = ha;
        Bs[0][bn4 + 0][bkr] = __float2half_rn(pb0.x);
        Bs[0][bn4 + 1][bkr] = __float2half_rn(pb0.y);
        Bs[0][bn4 + 2][bkr] = __float2half_rn(pb0.z);
        Bs[0][bn4 + 3][bkr] = __float2half_rn(pb0.w);
        Bs[0][bn4 + 64][bkr] = __float2half_rn(pb1.x);
        Bs[0][bn4 + 65][bkr] = __float2half_rn(pb1.y);
        Bs[0][bn4 + 66][bkr] = __float2half_rn(pb1.z);
        Bs[0][bn4 + 67][bkr] = __float2half_rn(pb1.w);
    }
    __syncthreads();

    float acc[4][4][4];
    #pragma unroll
    for (int mi = 0; mi < 4; ++mi)
        #pragma unroll
        for (int nf = 0; nf < 4; ++nf)
            #pragma unroll
            for (int r = 0; r < 4; ++r) acc[mi][nf][r] = 0.f;

    #pragma unroll 1
    for (int ch = 0; ch < ND / BK; ++ch) {
        const int cur = ch & 1;
        if (ch < ND / BK - 1) {
            pa0 = *(const float4*)(Aptr + (ch + 1) * BK);
            pa1 = *(const float4*)(Aptr + (ch + 1) * BK + 4);
            pb0 = *(const float4*)(Bptr + (size_t)(ch + 1) * BK * ND);
            pb1 = *(const float4*)(Bptr + (size_t)(ch + 1) * BK * ND + 64);
        }

        uint32_t afr[4][4];
        uint32_t bfr[4][2];
        #pragma unroll
        for (int mi = 0; mi < 4; ++mi) {
            const int m = warp_m + mi * 16 + g;
            afr[mi][0] = *(const uint32_t*)&As[cur][m    ][2 * c    ];
            afr[mi][1] = *(const uint32_t*)&As[cur][m + 8][2 * c    ];
            afr[mi][2] = *(const uint32_t*)&As[cur][m    ][2 * c + 8];
            afr[mi][3] = *(const uint32_t*)&As[cur][m + 8][2 * c + 8];
        }
        #pragma unroll
        for (int nf = 0; nf < 4; ++nf) {
            const int n = warp_n + nf * 8 + g;
            bfr[nf][0] = *(const uint32_t*)&Bs[cur][n][2 * c    ];
            bfr[nf][1] = *(const uint32_t*)&Bs[cur][n][2 * c + 8];
        }
        #pragma unroll
        for (int mi = 0; mi < 4; ++mi)
            #pragma unroll
            for (int nf = 0; nf < 4; ++nf)
                mma_f16_16816(acc[mi][nf], afr[mi], bfr[nf]);

        if (ch < ND / BK - 1) {
            const int nxt = cur ^ 1;
            uint2 ha;
            ha.x = pack_h2(pa0.x, pa0.y);  ha.y = pack_h2(pa0.z, pa0.w);
            *(uint2*)&As[nxt][am][ak] = ha;
            ha.x = pack_h2(pa1.x, pa1.y);  ha.y = pack_h2(pa1.z, pa1.w);
            *(uint2*)&As[nxt][am][ak + 4] = ha;
            Bs[nxt][bn4 + 0][bkr] = __float2half_rn(pb0.x);
            Bs[nxt][bn4 + 1][bkr] = __float2half_rn(pb0.y);
            Bs[nxt][bn4 + 2][bkr] = __float2half_rn(pb0.z);
            Bs[nxt][bn4 + 3][bkr] = __float2half_rn(pb0.w);
            Bs[nxt][bn4 + 64][bkr] = __float2half_rn(pb1.x);
            Bs[nxt][bn4 + 65][bkr] = __float2half_rn(pb1.y);
            Bs[nxt][bn4 + 66][bkr] = __float2half_rn(pb1.z);
            Bs[nxt][bn4 + 67][bkr] = __float2half_rn(pb1.w);
            __syncthreads();
        }
    }

    // epilogue: +bias (fp32), round to fp16, scatter to [B,H,L,Dh]
    const int h_base = (ncol0 >> 4) + (warp_n >> 4);
    #pragma unroll
    for (int mi = 0; mi < 4; ++mi) {
        const int r0 = by * 128 + warp_m + mi * 16 + g;
        const int r1 = r0 + 8;
        const int b0 = r0 / NL, l0 = r0 - b0 * NL;
        const int b1 = r1 / NL, l1 = r1 - b1 * NL;
        #pragma unroll
        for (int nf = 0; nf < 4; ++nf) {
            const int h = h_base + (nf >> 1);
            const int d = ((nf & 1) << 3) + 2 * c;       // even -> 4B aligned
            const float bi0 = bias[ncol0 + warp_n + nf * 8 + 2 * c];
            const float bi1 = bias[ncol0 + warp_n + nf * 8 + 2 * c + 1];
            __half* p0 = OUT + (((size_t)(b0 * NH + h) * NL + l0) << 4) + d;
            __half* p1 = OUT + (((size_t)(b1 * NH + h) * NL + l1) << 4) + d;
            uint32_t v0 = pack_h2(acc[mi][nf][0] + bi0, acc[mi][nf][1] + bi1);
            uint32_t v1 = pack_h2(acc[mi][nf][2] + bi0, acc[mi][nf][3] + bi1);
            *(uint32_t*)p0 = v0;
            *(uint32_t*)p1 = v1;
        }
    }
}

// ---------------- Kernel 2: fp16 tensor-core MHA per (b,h) ----------------
// 13 warps, exactly one 16-row tile per warp (no round-robin imbalance).
// S = Q K^T (m16n8k16); exp; S C-frag rounds to half2 -> PV A-frag directly.
#define AKST 24    // Q/K half-stride (12 words -> conflict-free bijection)
#define VTST 216   // Vt half-stride (108 words, 108%32==12 -> same bijection)
#define ATHREADS 416

__global__ __launch_bounds__(ATHREADS)
void attn_kernel(const int* __restrict__ his_mask)
{
    const int h = blockIdx.x;
    const int b = blockIdx.y;
    const int tid  = threadIdx.x;
    const int lane = tid & 31;
    const int wid  = tid >> 5;   // 0..12 -> tile index
    const int g = lane >> 2;     // row within 8
    const int c = lane & 3;      // quad col

    __shared__ __half Qs[208][AKST];     // rows 200..207 zeroed
    __shared__ __half Ks[200][AKST];
    __shared__ __half Vt[16][VTST];      // transposed V: [dh][key]
    __shared__ float  am[NL];

    const size_t base = (size_t)(b * NH + h) * NL * NDH;

    // Q/K: straight fp16 copy, 16B chunks
    for (int i = tid; i < NL * 2; i += ATHREADS) {
        const int row = i >> 1;
        const int p8  = (i & 1) * 8;
        *(uint4*)&Qs[row][p8] = *(const uint4*)(g_q + base + row * NDH + p8);
        *(uint4*)&Ks[row][p8] = *(const uint4*)(g_k + base + row * NDH + p8);
    }
    // V transpose: one row per thread
    for (int row = tid; row < NL; row += ATHREADS) {
        const uint4* vp = (const uint4*)(g_v + base + row * NDH);
        uint4 v0 = vp[0], v1 = vp[1];
        __half hbuf[16];
        *(uint4*)&hbuf[0] = v0;
        *(uint4*)&hbuf[8] = v1;
        #pragma unroll
        for (int d = 0; d < 16; ++d) Vt[d][row] = hbuf[d];
    }
    // zero Q pad rows (200..207)
    if (tid < 16) {
        const int row = 200 + (tid >> 1);
        const int p8  = (tid & 1) * 8;
        *(uint4*)&Qs[row][p8] = make_uint4(0, 0, 0, 0);
    }
    for (int i = tid; i < NL; i += ATHREADS)
        am[i] = (his_mask[b * NL + i] > 0) ? 0.f : -10000.f;
    __syncthreads();

    // one 16-row tile per warp
    {
        const int r0 = wid * 16;

        uint32_t aq[4];
        aq[0] = *(const uint32_t*)&Qs[r0 + g    ][2 * c    ];
        aq[1] = *(const uint32_t*)&Qs[r0 + g + 8][2 * c    ];
        aq[2] = *(const uint32_t*)&Qs[r0 + g    ][2 * c + 8];
        aq[3] = *(const uint32_t*)&Qs[r0 + g + 8][2 * c + 8];

        float ctx0[4] = {0.f, 0.f, 0.f, 0.f};   // dh 0..7
        float ctx1[4] = {0.f, 0.f, 0.f, 0.f};   // dh 8..15
        float sum_lo = 0.f, sum_hi = 0.f;

        for (int kc = 0; kc < NL / 8; ++kc) {
            const int k0 = kc * 8;

            uint32_t bk[2];
            bk[0] = *(const uint32_t*)&Ks[k0 + g][2 * c    ];
            bk[1] = *(const uint32_t*)&Ks[k0 + g][2 * c + 8];

            float s[4] = {0.f, 0.f, 0.f, 0.f};
            mma_f16_16816(s, aq, bk);

            const float a0 = am[k0 + 2 * c];
            const float a1 = am[k0 + 2 * c + 1];
            float p0 = __expf(fmaf(s[0], 0.25f, a0));
            float p1 = __expf(fmaf(s[1], 0.25f, a1));
            float p2 = __expf(fmaf(s[2], 0.25f, a0));
            float p3 = __expf(fmaf(s[3], 0.25f, a1));

            // round to fp16 ONCE; identical values feed numerator and denominator
            const uint32_t plo = pack_h2(p0, p1);   // A-frag a0 (row g)
            const uint32_t phi = pack_h2(p2, p3);   // A-frag a1 (row g+8)
            float2 flo = __half22float2(*(const __half2*)&plo);
            float2 fhi = __half22float2(*(const __half2*)&phi);
            sum_lo += flo.x + flo.y;
            sum_hi += fhi.x + fhi.y;

            const uint32_t bv0 = *(const uint32_t*)&Vt[g    ][k0 + 2 * c];
            const uint32_t bv1 = *(const uint32_t*)&Vt[g + 8][k0 + 2 * c];
            mma_f16_1688(ctx0, plo, phi, bv0);
            mma_f16_1688(ctx1, plo, phi, bv1);
        }

        sum_lo += __shfl_xor_sync(0xffffffffu, sum_lo, 1);
        sum_lo += __shfl_xor_sync(0xffffffffu, sum_lo, 2);
        sum_hi += __shfl_xor_sync(0xffffffffu, sum_hi, 1);
        sum_hi += __shfl_xor_sync(0xffffffffu, sum_hi, 2);
        const float inv_lo = 1.0f / sum_lo;
        const float inv_hi = 1.0f / sum_hi;

        const int row_lo = r0 + g;
        const int row_hi = r0 + g + 8;
        if (row_lo < NL) {
            __half* p = g_ctx + ((size_t)b * NL + row_lo) * ND + h * NDH;
            *(uint32_t*)(p + 2 * c)     = pack_h2(ctx0[0] * inv_lo, ctx0[1] * inv_lo);
            *(uint32_t*)(p + 8 + 2 * c) = pack_h2(ctx1[0] * inv_lo, ctx1[1] * inv_lo);
        }
        if (row_hi < NL) {
            __half* p = g_ctx + ((size_t)b * NL + row_hi) * ND + h * NDH;
            *(uint32_t*)(p + 2 * c)     = pack_h2(ctx0[2] * inv_hi, ctx0[3] * inv_hi);
            *(uint32_t*)(p + 8 + 2 * c) = pack_h2(ctx1[2] * inv_hi, ctx1[3] * inv_hi);
        }
    }
}

// ---------------- Kernel 3a: u = Wo @ query^T  (tiny) ----------------
__global__ __launch_bounds__(256)
void u_kernel(const float* __restrict__ Wo, const float* __restrict__ query)
{
    __shared__ float qs[ND];
    const int tid = threadIdx.x;
    qs[tid] = query[tid];
    __syncthreads();
    const float* row = Wo + (size_t)tid * ND;
    float a0 = 0.f, a1 = 0.f, a2 = 0.f, a3 = 0.f;
    #pragma unroll 8
    for (int n = 0; n < ND; n += 4) {
        a0 = fmaf(row[n + 0], qs[n + 0], a0);
        a1 = fmaf(row[n + 1], qs[n + 1], a1);
        a2 = fmaf(row[n + 2], qs[n + 2], a2);
        a3 = fmaf(row[n + 3], qs[n + 3], a3);
    }
    g_u[tid] = (a0 + a1) + (a2 + a3);
}

// ---------------- Kernel 3b: masked softmax pooling + projected epilogue ----------
// ctx is fp16 now: half the DRAM traffic of the two passes.
__global__ __launch_bounds__(256)
void pool_kernel(const float* __restrict__ Wo, const float* __restrict__ bo,
                 const int* __restrict__ his_mask, float* __restrict__ out)
{
    const int b    = blockIdx.x;
    const int tid  = threadIdx.x;
    const int lane = tid & 31;
    const int warp = tid >> 5;

    __shared__ float ps[NL];
    __shared__ float pooled[ND];
    __shared__ float red[8];

    const __half* C = g_ctx + (size_t)b * NL * ND;

    float4 ua = ((const float4*)g_u)[lane * 2];
    float4 ub = ((const float4*)g_u)[lane * 2 + 1];

    for (int l = warp; l < NL; l += 8) {
        const __half2* c2 = (const __half2*)(C + (size_t)l * ND + lane * 8);
        float2 x0 = __half22float2(c2[0]);
        float2 x1 = __half22float2(c2[1]);
        float2 x2 = __half22float2(c2[2]);
        float2 x3 = __half22float2(c2[3]);
        float acc = x0.x * ua.x + x0.y * ua.y + x1.x * ua.z + x1.y * ua.w
                  + x2.x * ub.x + x2.y * ub.y + x3.x * ub.z + x3.y * ub.w;
        #pragma unroll
        for (int o = 16; o; o >>= 1) acc += __shfl_xor_sync(0xffffffffu, acc, o);
        if (lane == 0)
            ps[l] = (his_mask[b * NL + l] > 0) ? acc * 0.0625f : -1e9f;
    }
    __syncthreads();

    float v = (tid < NL) ? ps[tid] : -3.0e38f;
    float mx = v;
    #pragma unroll
    for (int o = 16; o; o >>= 1) mx = fmaxf(mx, __shfl_xor_sync(0xffffffffu, mx, o));
    if (lane == 0) red[warp] = mx;
    __syncthreads();
    float bm = red[0];
    #pragma unroll
    for (int i = 1; i < 8; ++i) bm = fmaxf(bm, red[i]);

    float e = (tid < NL) ? __expf(v - bm) : 0.f;
    float sv = e;
    #pragma unroll
    for (int o = 16; o; o >>= 1) sv += __shfl_xor_sync(0xffffffffu, sv, o);
    __syncthreads();
    if (lane == 0) red[warp] = sv;
    if (tid < NL) ps[tid] = e;
    __syncthreads();
    float tot = (red[0] + red[1]) + (red[2] + red[3])
              + (red[4] + red[5]) + (red[6] + red[7]);
    float inv = 1.0f / tot;

    // pooled[d] = sum_l p[l] * ctx[b,l,d]
    {
        float a0 = 0.f, a1 = 0.f, a2 = 0.f, a3 = 0.f;
        const __half* Cd = C + tid;
        for (int l = 0; l < NL; l += 4) {
            a0 = fmaf(ps[l + 0], __half2float(Cd[(size_t)(l + 0) * ND]), a0);
            a1 = fmaf(ps[l + 1], __half2float(Cd[(size_t)(l + 1) * ND]), a1);
            a2 = fmaf(ps[l + 2], __half2float(Cd[(size_t)(l + 2) * ND]), a2);
            a3 = fmaf(ps[l + 3], __half2float(Cd[(size_t)(l + 3) * ND]), a3);
        }
        pooled[tid] = ((a0 + a1) + (a2 + a3)) * inv;
    }
    __syncthreads();

    float o = bo[tid];
    const float* Wn = Wo + tid;
    #pragma unroll 8
    for (int d = 0; d < ND; ++d) o = fmaf(pooled[d], Wn[(size_t)d * ND], o);
    out[(size_t)b * ND + tid] = o;
}

// ---------------- launch ----------------
extern "C" void kernel_launch(void* const* d_in, const int* in_sizes, int n_in,
                              void* d_out, int out_size)
{
    const float* news  = (const float*)d_in[0];
    const int*   hmask = (const int*)  d_in[1];
    const float* Wq    = (const float*)d_in[2];
    const float* bq    = (const float*)d_in[3];
    const float* Wk    = (const float*)d_in[4];
    const float* bk    = (const float*)d_in[5];
    const float* Wv    = (const float*)d_in[6];
    const float* bvv   = (const float*)d_in[7];
    const float* Wo    = (const float*)d_in[8];
    const float* bo    = (const float*)d_in[9];
    const float* query = (const float*)d_in[10];
    float* out = (float*)d_out;

    dim3 gemm_grid(6, (NB * NL) / 128);            // 6 x 400
    qkv_mma_kernel<<<gemm_grid, 256>>>(news, Wq, bq, Wk, bk, Wv, bvv);

    dim3 attn_grid(NH, NB);                        // 16 x 256
    attn_kernel<<<attn_grid, ATHREADS>>>(hmask);

    u_kernel<<<1, 256>>>(Wo, query);

    pool_kernel<<<NB, 256>>>(Wo, bo, hmask, out);
}

// round 16
// speedup vs baseline: 1.7965x; 1.2644x over previous
#include <cuda_runtime.h>
#include <cuda_fp16.h>
#include <cstdint>

#define NB   256   // batch
#define NL   200   // seq len
#define ND   256   // model dim
#define NH   16    // heads
#define NDH  16    // head dim

// ---------------- scratch (device globals: alloc-free) ----------------
__device__ __half g_a16[NB * NL * ND];       // news_repr as fp16 (row-major)
__device__ __half g_w16[3 * ND * ND];        // [Wq|Wk|Wv] transposed: [n][k] fp16
__device__ __half g_q[NB * NH * NL * NDH];   // [B,H,L,Dh] fp16
__device__ __half g_k[NB * NH * NL * NDH];
__device__ __half g_v[NB * NH * NL * NDH];
__device__ __half g_ctx[NB * NL * ND];       // [B,L,D] fp16
__device__ float  g_u[ND];                   // Wo @ query^T (fp32)

// ---------------- helpers ----------------
__device__ __forceinline__ uint32_t pack_h2(float a, float b) {
    __half2 h = __floats2half2_rn(a, b);
    return *(uint32_t*)&h;
}

__device__ __forceinline__ void mma_f16_16816(float* d,
                                              const uint32_t* a,
                                              const uint32_t* b)
{
    asm volatile(
        "mma.sync.aligned.m16n8k16.row.col.f32.f16.f16.f32 "
        "{%0,%1,%2,%3}, {%4,%5,%6,%7}, {%8,%9}, {%0,%1,%2,%3};\n"
        : "+f"(d[0]), "+f"(d[1]), "+f"(d[2]), "+f"(d[3])
        : "r"(a[0]), "r"(a[1]), "r"(a[2]), "r"(a[3]),
          "r"(b[0]), "r"(b[1]));
}

__device__ __forceinline__ void mma_f16_1688(float* d,
                                             uint32_t a0, uint32_t a1,
                                             uint32_t b0)
{
    asm volatile(
        "mma.sync.aligned.m16n8k8.row.col.f32.f16.f16.f32 "
        "{%0,%1,%2,%3}, {%4,%5}, {%6}, {%0,%1,%2,%3};\n"
        : "+f"(d[0]), "+f"(d[1]), "+f"(d[2]), "+f"(d[3])
        : "r"(a0), "r"(a1), "r"(b0));
}

__device__ __forceinline__ void cp16(uint32_t smem_dst, const void* gmem_src) {
    asm volatile("cp.async.cg.shared.global [%0], [%1], 16;"
                 :: "r"(smem_dst), "l"(gmem_src));
}
#define CP_COMMIT() asm volatile("cp.async.commit_group;" ::: "memory")
#define CP_WAIT0()  asm volatile("cp.async.wait_group 0;" ::: "memory")

// ---------------- Kernel 0a: news_repr fp32 -> fp16 ----------------
__global__ __launch_bounds__(256)
void a_convert_kernel(const float* __restrict__ A)
{
    const size_t idx = (size_t)blockIdx.x * 256 + threadIdx.x;   // 8 floats each
    const float4* src = (const float4*)A + idx * 2;
    float4 v0 = src[0], v1 = src[1];
    uint4 o;
    o.x = pack_h2(v0.x, v0.y);
    o.y = pack_h2(v0.z, v0.w);
    o.z = pack_h2(v1.x, v1.y);
    o.w = pack_h2(v1.z, v1.w);
    *((uint4*)g_a16 + idx) = o;
}

// ---------------- Kernel 0b: W fp32 -> fp16 transposed [n][k] ----------------
__global__ __launch_bounds__(256)
void w_convert_kernel(const float* __restrict__ Wq,
                      const float* __restrict__ Wk,
                      const float* __restrict__ Wv)
{
    const int k   = blockIdx.x;       // 0..255
    const int mat = blockIdx.y;       // 0..2
    const int n   = threadIdx.x;      // 0..255
    const float* W = (mat == 0) ? Wq : (mat == 1 ? Wk : Wv);
    const float v = W[k * ND + n];    // coalesced read
    g_w16[((size_t)mat * ND + n) * ND + k] = __float2half_rn(v);
}

// ---------------- Kernel 1: QKV projection, fp16 mma + cp.async ----------------
// C[51200, 768] = A @ [Wq|Wk|Wv] + bias -> fp16 scatter to [B,H,L,Dh].
// Block tile 128x128, k-chunk 16, cp.async double-buffered, 8 warps (2Mx4N).
#define BK 16
#define QST 24   // half-stride (12 words): frag banks (12g+c) = full bijection mod 32

__global__ __launch_bounds__(256, 2)
void qkv_mma_kernel(const float* __restrict__ bq,
                    const float* __restrict__ bk,
                    const float* __restrict__ bvec)
{
    __shared__ __half As[2][128][QST];   // [m][k] row-major
    __shared__ __half Bs[2][128][QST];   // [n][k]

    const int tid = threadIdx.x;
    const int bx  = blockIdx.x;          // 0..5 : N-slab of 128 within [Q|K|V]
    const int by  = blockIdx.y;          // 0..399

    const int mat   = bx >> 1;           // 0=Q,1=K,2=V
    const int ncol0 = (bx & 1) * 128;

    const float* __restrict__ bias = (mat == 0) ? bq : (mat == 1 ? bk : bvec);
    __half* OUT = (mat == 0) ? g_q : (mat == 1 ? g_k : g_v);

    const int lane = tid & 31;
    const int wid  = tid >> 5;
    const int warp_m = (wid & 1) * 64;   // 0 or 64
    const int warp_n = (wid >> 1) * 32;  // 0,32,64,96
    const int g = lane >> 2;             // row within 8
    const int c = lane & 3;              // quad col

    // loaders: each thread copies one 16B chunk for A and one for B per k-chunk
    const int am = tid & 127;
    const int ak = (tid >> 7) * 8;       // 0 or 8
    const __half* Asrc = g_a16 + (size_t)(by * 128 + am) * ND + ak;
    const __half* Bsrc = g_w16 + ((size_t)mat * ND + ncol0 + am) * ND + ak;

    const uint32_t dstA[2] = {
        (uint32_t)__cvta_generic_to_shared(&As[0][am][ak]),
        (uint32_t)__cvta_generic_to_shared(&As[1][am][ak]) };
    const uint32_t dstB[2] = {
        (uint32_t)__cvta_generic_to_shared(&Bs[0][am][ak]),
        (uint32_t)__cvta_generic_to_shared(&Bs[1][am][ak]) };

    // prologue: chunk 0 into buffer 0
    cp16(dstA[0], Asrc);
    cp16(dstB[0], Bsrc);
    CP_COMMIT();
    CP_WAIT0();
    __syncthreads();

    float acc[4][4][4];
    #pragma unroll
    for (int mi = 0; mi < 4; ++mi)
        #pragma unroll
        for (int nf = 0; nf < 4; ++nf)
            #pragma unroll
            for (int r = 0; r < 4; ++r) acc[mi][nf][r] = 0.f;

    #pragma unroll 1
    for (int ch = 0; ch < ND / BK; ++ch) {
        const int cur = ch & 1;
        if (ch < ND / BK - 1) {
            const int nxt = cur ^ 1;
            cp16(dstA[nxt], Asrc + (ch + 1) * BK);
            cp16(dstB[nxt], Bsrc + (ch + 1) * BK);
            CP_COMMIT();
        }

        uint32_t afr[4][4];
        uint32_t bfr[4][2];
        #pragma unroll
        for (int mi = 0; mi < 4; ++mi) {
            const int m = warp_m + mi * 16 + g;
            afr[mi][0] = *(const uint32_t*)&As[cur][m    ][2 * c    ];
            afr[mi][1] = *(const uint32_t*)&As[cur][m + 8][2 * c    ];
            afr[mi][2] = *(const uint32_t*)&As[cur][m    ][2 * c + 8];
            afr[mi][3] = *(const uint32_t*)&As[cur][m + 8][2 * c + 8];
        }
        #pragma unroll
        for (int nf = 0; nf < 4; ++nf) {
            const int n = warp_n + nf * 8 + g;
            bfr[nf][0] = *(const uint32_t*)&Bs[cur][n][2 * c    ];
            bfr[nf][1] = *(const uint32_t*)&Bs[cur][n][2 * c + 8];
        }
        #pragma unroll
        for (int mi = 0; mi < 4; ++mi)
            #pragma unroll
            for (int nf = 0; nf < 4; ++nf)
                mma_f16_16816(acc[mi][nf], afr[mi], bfr[nf]);

        if (ch < ND / BK - 1) {
            CP_WAIT0();
            __syncthreads();
        }
    }

    // epilogue: +bias (fp32), round to fp16, scatter to [B,H,L,Dh]
    const int h_base = (ncol0 >> 4) + (warp_n >> 4);
    #pragma unroll
    for (int mi = 0; mi < 4; ++mi) {
        const int r0 = by * 128 + warp_m + mi * 16 + g;
        const int r1 = r0 + 8;
        const int b0 = r0 / NL, l0 = r0 - b0 * NL;
        const int b1 = r1 / NL, l1 = r1 - b1 * NL;
        #pragma unroll
        for (int nf = 0; nf < 4; ++nf) {
            const int h = h_base + (nf >> 1);
            const int d = ((nf & 1) << 3) + 2 * c;       // even -> 4B aligned
            const float bi0 = bias[ncol0 + warp_n + nf * 8 + 2 * c];
            const float bi1 = bias[ncol0 + warp_n + nf * 8 + 2 * c + 1];
            __half* p0 = OUT + (((size_t)(b0 * NH + h) * NL + l0) << 4) + d;
            __half* p1 = OUT + (((size_t)(b1 * NH + h) * NL + l1) << 4) + d;
            uint32_t v0 = pack_h2(acc[mi][nf][0] + bi0, acc[mi][nf][1] + bi1);
            uint32_t v1 = pack_h2(acc[mi][nf][2] + bi0, acc[mi][nf][3] + bi1);
            *(uint32_t*)p0 = v0;
            *(uint32_t*)p1 = v1;
        }
    }
}

// ---------------- Kernel 2: fp16 tensor-core MHA per (b,h) ----------------
// 13 warps, one 16-row tile per warp.
// S = Q K^T (m16n8k16); exp; S C-frag rounds to half2 -> PV A-frag directly.
#define AKST 24    // Q/K half-stride (12 words -> conflict-free bijection)
#define VTST 216   // Vt half-stride (108 words, 108%32==12 -> same bijection)
#define ATHREADS 416

__global__ __launch_bounds__(ATHREADS)
void attn_kernel(const int* __restrict__ his_mask)
{
    const int h = blockIdx.x;
    const int b = blockIdx.y;
    const int tid  = threadIdx.x;
    const int lane = tid & 31;
    const int wid  = tid >> 5;   // 0..12 -> tile index
    const int g = lane >> 2;     // row within 8
    const int c = lane & 3;      // quad col

    __shared__ __half Qs[208][AKST];     // rows 200..207 zeroed
    __shared__ __half Ks[200][AKST];
    __shared__ __half Vt[16][VTST];      // transposed V: [dh][key]
    __shared__ float  am[NL];

    const size_t base = (size_t)(b * NH + h) * NL * NDH;

    // Q/K: straight fp16 copy, 16B chunks
    for (int i = tid; i < NL * 2; i += ATHREADS) {
        const int row = i >> 1;
        const int p8  = (i & 1) * 8;
        *(uint4*)&Qs[row][p8] = *(const uint4*)(g_q + base + row * NDH + p8);
        *(uint4*)&Ks[row][p8] = *(const uint4*)(g_k + base + row * NDH + p8);
    }
    // V transpose: one row per thread
    for (int row = tid; row < NL; row += ATHREADS) {
        const uint4* vp = (const uint4*)(g_v + base + row * NDH);
        uint4 v0 = vp[0], v1 = vp[1];
        __half hbuf[16];
        *(uint4*)&hbuf[0] = v0;
        *(uint4*)&hbuf[8] = v1;
        #pragma unroll
        for (int d = 0; d < 16; ++d) Vt[d][row] = hbuf[d];
    }
    // zero Q pad rows (200..207)
    if (tid < 16) {
        const int row = 200 + (tid >> 1);
        const int p8  = (tid & 1) * 8;
        *(uint4*)&Qs[row][p8] = make_uint4(0, 0, 0, 0);
    }
    for (int i = tid; i < NL; i += ATHREADS)
        am[i] = (his_mask[b * NL + i] > 0) ? 0.f : -10000.f;
    __syncthreads();

    // one 16-row tile per warp
    {
        const int r0 = wid * 16;

        uint32_t aq[4];
        aq[0] = *(const uint32_t*)&Qs[r0 + g    ][2 * c    ];
        aq[1] = *(const uint32_t*)&Qs[r0 + g + 8][2 * c    ];
        aq[2] = *(const uint32_t*)&Qs[r0 + g    ][2 * c + 8];
        aq[3] = *(const uint32_t*)&Qs[r0 + g + 8][2 * c + 8];

        float ctx0[4] = {0.f, 0.f, 0.f, 0.f};   // dh 0..7
        float ctx1[4] = {0.f, 0.f, 0.f, 0.f};   // dh 8..15
        float sum_lo = 0.f, sum_hi = 0.f;

        for (int kc = 0; kc < NL / 8; ++kc) {
            const int k0 = kc * 8;

            uint32_t bk[2];
            bk[0] = *(const uint32_t*)&Ks[k0 + g][2 * c    ];
            bk[1] = *(const uint32_t*)&Ks[k0 + g][2 * c + 8];

            float s[4] = {0.f, 0.f, 0.f, 0.f};
            mma_f16_16816(s, aq, bk);

            const float a0 = am[k0 + 2 * c];
            const float a1 = am[k0 + 2 * c + 1];
            float p0 = __expf(fmaf(s[0], 0.25f, a0));
            float p1 = __expf(fmaf(s[1], 0.25f, a1));
            float p2 = __expf(fmaf(s[2], 0.25f, a0));
            float p3 = __expf(fmaf(s[3], 0.25f, a1));

            // round to fp16 ONCE; identical values feed numerator and denominator
            const uint32_t plo = pack_h2(p0, p1);   // A-frag a0 (row g)
            const uint32_t phi = pack_h2(p2, p3);   // A-frag a1 (row g+8)
            float2 flo = __half22float2(*(const __half2*)&plo);
            float2 fhi = __half22float2(*(const __half2*)&phi);
            sum_lo += flo.x + flo.y;
            sum_hi += fhi.x + fhi.y;

            const uint32_t bv0 = *(const uint32_t*)&Vt[g    ][k0 + 2 * c];
            const uint32_t bv1 = *(const uint32_t*)&Vt[g + 8][k0 + 2 * c];
            mma_f16_1688(ctx0, plo, phi, bv0);
            mma_f16_1688(ctx1, plo, phi, bv1);
        }

        sum_lo += __shfl_xor_sync(0xffffffffu, sum_lo, 1);
        sum_lo += __shfl_xor_sync(0xffffffffu, sum_lo, 2);
        sum_hi += __shfl_xor_sync(0xffffffffu, sum_hi, 1);
        sum_hi += __shfl_xor_sync(0xffffffffu, sum_hi, 2);
        const float inv_lo = 1.0f / sum_lo;
        const float inv_hi = 1.0f / sum_hi;

        const int row_lo = r0 + g;
        const int row_hi = r0 + g + 8;
        if (row_lo < NL) {
            __half* p = g_ctx + ((size_t)b * NL + row_lo) * ND + h * NDH;
            *(uint32_t*)(p + 2 * c)     = pack_h2(ctx0[0] * inv_lo, ctx0[1] * inv_lo);
            *(uint32_t*)(p + 8 + 2 * c) = pack_h2(ctx1[0] * inv_lo, ctx1[1] * inv_lo);
        }
        if (row_hi < NL) {
            __half* p = g_ctx + ((size_t)b * NL + row_hi) * ND + h * NDH;
            *(uint32_t*)(p + 2 * c)     = pack_h2(ctx0[2] * inv_hi, ctx0[3] * inv_hi);
            *(uint32_t*)(p + 8 + 2 * c) = pack_h2(ctx1[2] * inv_hi, ctx1[3] * inv_hi);
        }
    }
}

// ---------------- Kernel 3a: u = Wo @ query^T  (tiny) ----------------
__global__ __launch_bounds__(256)
void u_kernel(const float* __restrict__ Wo, const float* __restrict__ query)
{
    __shared__ float qs[ND];
    const int tid = threadIdx.x;
    qs[tid] = query[tid];
    __syncthreads();
    const float* row = Wo + (size_t)tid * ND;
    float a0 = 0.f, a1 = 0.f, a2 = 0.f, a3 = 0.f;
    #pragma unroll 8
    for (int n = 0; n < ND; n += 4) {
        a0 = fmaf(row[n + 0], qs[n + 0], a0);
        a1 = fmaf(row[n + 1], qs[n + 1], a1);
        a2 = fmaf(row[n + 2], qs[n + 2], a2);
        a3 = fmaf(row[n + 3], qs[n + 3], a3);
    }
    g_u[tid] = (a0 + a1) + (a2 + a3);
}

// ---------------- Kernel 3b: masked softmax pooling + projected epilogue ----------
__global__ __launch_bounds__(256)
void pool_kernel(const float* __restrict__ Wo, const float* __restrict__ bo,
                 const int* __restrict__ his_mask, float* __restrict__ out)
{
    const int b    = blockIdx.x;
    const int tid  = threadIdx.x;
    const int lane = tid & 31;
    const int warp = tid >> 5;

    __shared__ float ps[NL];
    __shared__ float pooled[ND];
    __shared__ float red[8];

    const __half* C = g_ctx + (size_t)b * NL * ND;

    float4 ua = ((const float4*)g_u)[lane * 2];
    float4 ub = ((const float4*)g_u)[lane * 2 + 1];

    for (int l = warp; l < NL; l += 8) {
        const __half2* c2 = (const __half2*)(C + (size_t)l * ND + lane * 8);
        float2 x0 = __half22float2(c2[0]);
        float2 x1 = __half22float2(c2[1]);
        float2 x2 = __half22float2(c2[2]);
        float2 x3 = __half22float2(c2[3]);
        float acc = x0.x * ua.x + x0.y * ua.y + x1.x * ua.z + x1.y * ua.w
                  + x2.x * ub.x + x2.y * ub.y + x3.x * ub.z + x3.y * ub.w;
        #pragma unroll
        for (int o = 16; o; o >>= 1) acc += __shfl_xor_sync(0xffffffffu, acc, o);
        if (lane == 0)
            ps[l] = (his_mask[b * NL + l] > 0) ? acc * 0.0625f : -1e9f;
    }
    __syncthreads();

    float v = (tid < NL) ? ps[tid] : -3.0e38f;
    float mx = v;
    #pragma unroll
    for (int o = 16; o; o >>= 1) mx = fmaxf(mx, __shfl_xor_sync(0xffffffffu, mx, o));
    if (lane == 0) red[warp] = mx;
    __syncthreads();
    float bm = red[0];
    #pragma unroll
    for (int i = 1; i < 8; ++i) bm = fmaxf(bm, red[i]);

    float e = (tid < NL) ? __expf(v - bm) : 0.f;
    float sv = e;
    #pragma unroll
    for (int o = 16; o; o >>= 1) sv += __shfl_xor_sync(0xffffffffu, sv, o);
    __syncthreads();
    if (lane == 0) red[warp] = sv;
    if (tid < NL) ps[tid] = e;
    __syncthreads();
    float tot = (red[0] + red[1]) + (red[2] + red[3])
              + (red[4] + red[5]) + (red[6] + red[7]);
    float inv = 1.0f / tot;

    // pooled[d] = sum_l p[l] * ctx[b,l,d]
    {
        float a0 = 0.f, a1 = 0.f, a2 = 0.f, a3 = 0.f;
        const __half* Cd = C + tid;
        for (int l = 0; l < NL; l += 4) {
            a0 = fmaf(ps[l + 0], __half2float(Cd[(size_t)(l + 0) * ND]), a0);
            a1 = fmaf(ps[l + 1], __half2float(Cd[(size_t)(l + 1) * ND]), a1);
            a2 = fmaf(ps[l + 2], __half2float(Cd[(size_t)(l + 2) * ND]), a2);
            a3 = fmaf(ps[l + 3], __half2float(Cd[(size_t)(l + 3) * ND]), a3);
        }
        pooled[tid] = ((a0 + a1) + (a2 + a3)) * inv;
    }
    __syncthreads();

    float o = bo[tid];
    const float* Wn = Wo + tid;
    #pragma unroll 8
    for (int d = 0; d < ND; ++d) o = fmaf(pooled[d], Wn[(size_t)d * ND], o);
    out[(size_t)b * ND + tid] = o;
}

// ---------------- launch ----------------
extern "C" void kernel_launch(void* const* d_in, const int* in_sizes, int n_in,
                              void* d_out, int out_size)
{
    const float* news  = (const float*)d_in[0];
    const int*   hmask = (const int*)  d_in[1];
    const float* Wq    = (const float*)d_in[2];
    const float* bq    = (const float*)d_in[3];
    const float* Wk    = (const float*)d_in[4];
    const float* bk    = (const float*)d_in[5];
    const float* Wv    = (const float*)d_in[6];
    const float* bvv   = (const float*)d_in[7];
    const float* Wo    = (const float*)d_in[8];
    const float* bo    = (const float*)d_in[9];
    const float* query = (const float*)d_in[10];
    float* out = (float*)d_out;

    a_convert_kernel<<<(NB * NL * ND) / (8 * 256), 256>>>(news);   // 6400 blocks
    dim3 wgrid(ND, 3);
    w_convert_kernel<<<wgrid, 256>>>(Wq, Wk, Wv);

    dim3 gemm_grid(6, (NB * NL) / 128);            // 6 x 400
    qkv_mma_kernel<<<gemm_grid, 256>>>(bq, bk, bvv);

    dim3 attn_grid(NH, NB);                        // 16 x 256
    attn_kernel<<<attn_grid, ATHREADS>>>(hmask);

    u_kernel<<<1, 256>>>(Wo, query);

    pool_kernel<<<NB, 256>>>(Wo, bo, hmask, out);
}

// round 17
// speedup vs baseline: 1.9352x; 1.0772x over previous
#include <cuda_runtime.h>
#include <cuda_fp16.h>
#include <cstdint>

#define NB   256   // batch
#define NL   200   // seq len
#define NLP  208   // padded seq len (13 x 16)
#define ND   256   // model dim
#define NH   16    // heads
#define NDH  16    // head dim

// ---------------- scratch (device globals: alloc-free) ----------------
__device__ __half g_a16[NB * NL * ND];       // news_repr as fp16 (row-major)
__device__ __half g_w16[3 * ND * ND];        // [Wq|Wk|Wv] transposed: [n][k] fp16
__device__ __half g_q[NB * NH * NL * NDH];   // [B,H,L,Dh] fp16
__device__ __half g_k[NB * NH * NL * NDH];
__device__ __half g_v[NB * NH * NL * NDH];
__device__ __half g_ctx[NB * NL * ND];       // [B,L,D] fp16
__device__ float  g_u[ND];                   // Wo @ query^T (fp32)

// ---------------- helpers ----------------
__device__ __forceinline__ uint32_t pack_h2(float a, float b) {
    __half2 h = __floats2half2_rn(a, b);
    return *(uint32_t*)&h;
}

__device__ __forceinline__ uint32_t ex2_f16x2(uint32_t y2) {
    uint32_t r;
    asm("ex2.approx.f16x2 %0, %1;" : "=r"(r) : "r"(y2));
    return r;
}

__device__ __forceinline__ void mma_f16_16816(float* d,
                                              const uint32_t* a,
                                              const uint32_t* b)
{
    asm volatile(
        "mma.sync.aligned.m16n8k16.row.col.f32.f16.f16.f32 "
        "{%0,%1,%2,%3}, {%4,%5,%6,%7}, {%8,%9}, {%0,%1,%2,%3};\n"
        : "+f"(d[0]), "+f"(d[1]), "+f"(d[2]), "+f"(d[3])
        : "r"(a[0]), "r"(a[1]), "r"(a[2]), "r"(a[3]),
          "r"(b[0]), "r"(b[1]));
}

__device__ __forceinline__ void cp16(uint32_t smem_dst, const void* gmem_src) {
    asm volatile("cp.async.cg.shared.global [%0], [%1], 16;"
                 :: "r"(smem_dst), "l"(gmem_src));
}
#define CP_COMMIT() asm volatile("cp.async.commit_group;" ::: "memory")
#define CP_WAIT0()  asm volatile("cp.async.wait_group 0;" ::: "memory")

// ---------------- Kernel 0a: news_repr fp32 -> fp16 ----------------
__global__ __launch_bounds__(256)
void a_convert_kernel(const float* __restrict__ A)
{
    const size_t idx = (size_t)blockIdx.x * 256 + threadIdx.x;   // 8 floats each
    const float4* src = (const float4*)A + idx * 2;
    float4 v0 = src[0], v1 = src[1];
    uint4 o;
    o.x = pack_h2(v0.x, v0.y);
    o.y = pack_h2(v0.z, v0.w);
    o.z = pack_h2(v1.x, v1.y);
    o.w = pack_h2(v1.z, v1.w);
    *((uint4*)g_a16 + idx) = o;
}

// ---------------- Kernel 0b: W fp32 -> fp16 transposed [n][k] ----------------
__global__ __launch_bounds__(256)
void w_convert_kernel(const float* __restrict__ Wq,
                      const float* __restrict__ Wk,
                      const float* __restrict__ Wv)
{
    const int k   = blockIdx.x;       // 0..255
    const int mat = blockIdx.y;       // 0..2
    const int n   = threadIdx.x;      // 0..255
    const float* W = (mat == 0) ? Wq : (mat == 1 ? Wk : Wv);
    const float v = W[k * ND + n];    // coalesced read
    g_w16[((size_t)mat * ND + n) * ND + k] = __float2half_rn(v);
}

// ---------------- Kernel 1: QKV projection, fp16 mma + cp.async ----------------
#define BK 16
#define QST 24   // half-stride (12 words): frag banks (12g+c) = full bijection mod 32

__global__ __launch_bounds__(256, 2)
void qkv_mma_kernel(const float* __restrict__ bq,
                    const float* __restrict__ bk,
                    const float* __restrict__ bvec)
{
    __shared__ __half As[2][128][QST];   // [m][k] row-major
    __shared__ __half Bs[2][128][QST];   // [n][k]

    const int tid = threadIdx.x;
    const int bx  = blockIdx.x;          // 0..5
    const int by  = blockIdx.y;          // 0..399

    const int mat   = bx >> 1;           // 0=Q,1=K,2=V
    const int ncol0 = (bx & 1) * 128;

    const float* __restrict__ bias = (mat == 0) ? bq : (mat == 1 ? bk : bvec);
    __half* OUT = (mat == 0) ? g_q : (mat == 1 ? g_k : g_v);

    const int lane = tid & 31;
    const int wid  = tid >> 5;
    const int warp_m = (wid & 1) * 64;
    const int warp_n = (wid >> 1) * 32;
    const int g = lane >> 2;
    const int c = lane & 3;

    const int am = tid & 127;
    const int ak = (tid >> 7) * 8;       // 0 or 8
    const __half* Asrc = g_a16 + (size_t)(by * 128 + am) * ND + ak;
    const __half* Bsrc = g_w16 + ((size_t)mat * ND + ncol0 + am) * ND + ak;

    const uint32_t dstA[2] = {
        (uint32_t)__cvta_generic_to_shared(&As[0][am][ak]),
        (uint32_t)__cvta_generic_to_shared(&As[1][am][ak]) };
    const uint32_t dstB[2] = {
        (uint32_t)__cvta_generic_to_shared(&Bs[0][am][ak]),
        (uint32_t)__cvta_generic_to_shared(&Bs[1][am][ak]) };

    cp16(dstA[0], Asrc);
    cp16(dstB[0], Bsrc);
    CP_COMMIT();
    CP_WAIT0();
    __syncthreads();

    float acc[4][4][4];
    #pragma unroll
    for (int mi = 0; mi < 4; ++mi)
        #pragma unroll
        for (int nf = 0; nf < 4; ++nf)
            #pragma unroll
            for (int r = 0; r < 4; ++r) acc[mi][nf][r] = 0.f;

    #pragma unroll 1
    for (int ch = 0; ch < ND / BK; ++ch) {
        const int cur = ch & 1;
        if (ch < ND / BK - 1) {
            const int nxt = cur ^ 1;
            cp16(dstA[nxt], Asrc + (ch + 1) * BK);
            cp16(dstB[nxt], Bsrc + (ch + 1) * BK);
            CP_COMMIT();
        }

        uint32_t afr[4][4];
        uint32_t bfr[4][2];
        #pragma unroll
        for (int mi = 0; mi < 4; ++mi) {
            const int m = warp_m + mi * 16 + g;
            afr[mi][0] = *(const uint32_t*)&As[cur][m    ][2 * c    ];
            afr[mi][1] = *(const uint32_t*)&As[cur][m + 8][2 * c    ];
            afr[mi][2] = *(const uint32_t*)&As[cur][m    ][2 * c + 8];
            afr[mi][3] = *(const uint32_t*)&As[cur][m + 8][2 * c + 8];
        }
        #pragma unroll
        for (int nf = 0; nf < 4; ++nf) {
            const int n = warp_n + nf * 8 + g;
            bfr[nf][0] = *(const uint32_t*)&Bs[cur][n][2 * c    ];
            bfr[nf][1] = *(const uint32_t*)&Bs[cur][n][2 * c + 8];
        }
        #pragma unroll
        for (int mi = 0; mi < 4; ++mi)
            #pragma unroll
            for (int nf = 0; nf < 4; ++nf)
                mma_f16_16816(acc[mi][nf], afr[mi], bfr[nf]);

        if (ch < ND / BK - 1) {
            CP_WAIT0();
            __syncthreads();
        }
    }

    const int h_base = (ncol0 >> 4) + (warp_n >> 4);
    #pragma unroll
    for (int mi = 0; mi < 4; ++mi) {
        const int r0 = by * 128 + warp_m + mi * 16 + g;
        const int r1 = r0 + 8;
        const int b0 = r0 / NL, l0 = r0 - b0 * NL;
        const int b1 = r1 / NL, l1 = r1 - b1 * NL;
        #pragma unroll
        for (int nf = 0; nf < 4; ++nf) {
            const int h = h_base + (nf >> 1);
            const int d = ((nf & 1) << 3) + 2 * c;
            const float bi0 = bias[ncol0 + warp_n + nf * 8 + 2 * c];
            const float bi1 = bias[ncol0 + warp_n + nf * 8 + 2 * c + 1];
            __half* p0 = OUT + (((size_t)(b0 * NH + h) * NL + l0) << 4) + d;
            __half* p1 = OUT + (((size_t)(b1 * NH + h) * NL + l1) << 4) + d;
            uint32_t v0 = pack_h2(acc[mi][nf][0] + bi0, acc[mi][nf][1] + bi1);
            uint32_t v1 = pack_h2(acc[mi][nf][2] + bi0, acc[mi][nf][3] + bi1);
            *(uint32_t*)p0 = v0;
            *(uint32_t*)p1 = v1;
        }
    }
}

// ---------------- Kernel 2: fp16 tensor-core MHA per (b,h) ----------------
// 16-key chunks: S via 2x m16n8k16; exp via ex2.approx.f16x2 (mask+scale folded,
// log2-domain); exp'd half2 pairs ARE the PV m16n8k16 A-frag; row sums via a
// ones-B mma (fp32 acc, no shuffles). Keys padded to 208 (K rows/Vt cols zeroed,
// am=masked -> exp == exact 0).
#define AKST 24    // Q/K half-stride (12 words -> conflict-free bijection)
#define VTST 216   // Vt half-stride
#define ATHREADS 416
#define EXSC 0.360673760f      // 0.25 * log2(e)
#define MASKVAL -14427.0f      // -10000 * log2(e)

__global__ __launch_bounds__(ATHREADS)
void attn_kernel(const int* __restrict__ his_mask)
{
    const int h = blockIdx.x;
    const int b = blockIdx.y;
    const int tid  = threadIdx.x;
    const int lane = tid & 31;
    const int wid  = tid >> 5;   // 0..12 -> tile index
    const int g = lane >> 2;     // row within 8
    const int c = lane & 3;      // quad col

    __shared__ __half Qs[NLP][AKST];     // rows 200..207 zeroed
    __shared__ __half Ks[NLP][AKST];     // rows 200..207 zeroed
    __shared__ __half Vt[16][VTST];      // transposed V; cols 200..207 zeroed
    __shared__ float  am[NLP];           // log2-scaled additive mask

    const size_t base = (size_t)(b * NH + h) * NL * NDH;

    // Q/K: straight fp16 copy, 16B chunks
    for (int i = tid; i < NL * 2; i += ATHREADS) {
        const int row = i >> 1;
        const int p8  = (i & 1) * 8;
        *(uint4*)&Qs[row][p8] = *(const uint4*)(g_q + base + row * NDH + p8);
        *(uint4*)&Ks[row][p8] = *(const uint4*)(g_k + base + row * NDH + p8);
    }
    // V transpose: one row per thread
    for (int row = tid; row < NL; row += ATHREADS) {
        const uint4* vp = (const uint4*)(g_v + base + row * NDH);
        uint4 v0 = vp[0], v1 = vp[1];
        __half hbuf[16];
        *(uint4*)&hbuf[0] = v0;
        *(uint4*)&hbuf[8] = v1;
        #pragma unroll
        for (int d = 0; d < 16; ++d) Vt[d][row] = hbuf[d];
    }
    // zero pads: Q rows (tid 0..15), K rows (tid 16..31), Vt cols (tid 32..159)
    if (tid < 16) {
        const int row = 200 + (tid >> 1);
        const int p8  = (tid & 1) * 8;
        *(uint4*)&Qs[row][p8] = make_uint4(0, 0, 0, 0);
    } else if (tid < 32) {
        const int t = tid - 16;
        const int row = 200 + (t >> 1);
        const int p8  = (t & 1) * 8;
        *(uint4*)&Ks[row][p8] = make_uint4(0, 0, 0, 0);
    } else if (tid < 160) {
        const int t = tid - 32;
        Vt[t >> 3][200 + (t & 7)] = __ushort_as_half((unsigned short)0);
    }
    for (int i = tid; i < NLP; i += ATHREADS)
        am[i] = (i < NL && his_mask[b * NL + i] > 0) ? 0.f : MASKVAL;
    __syncthreads();

    // one 16-row tile per warp
    {
        const int r0 = wid * 16;

        uint32_t aq[4];
        aq[0] = *(const uint32_t*)&Qs[r0 + g    ][2 * c    ];
        aq[1] = *(const uint32_t*)&Qs[r0 + g + 8][2 * c    ];
        aq[2] = *(const uint32_t*)&Qs[r0 + g    ][2 * c + 8];
        aq[3] = *(const uint32_t*)&Qs[r0 + g + 8][2 * c + 8];

        float ctx0[4] = {0.f, 0.f, 0.f, 0.f};   // dh 0..7
        float ctx1[4] = {0.f, 0.f, 0.f, 0.f};   // dh 8..15
        float sacc[4] = {0.f, 0.f, 0.f, 0.f};   // row sums via ones-mma
        const uint32_t ones2[2] = {0x3C003C00u, 0x3C003C00u};

        for (int kc = 0; kc < NLP / 16; ++kc) {
            const int k0 = kc * 16;

            // S for keys k0..k0+7 and k0+8..k0+15 (two n=8 mmas)
            uint32_t bk1[2], bk2[2];
            bk1[0] = *(const uint32_t*)&Ks[k0 + g    ][2 * c    ];
            bk1[1] = *(const uint32_t*)&Ks[k0 + g    ][2 * c + 8];
            bk2[0] = *(const uint32_t*)&Ks[k0 + 8 + g][2 * c    ];
            bk2[1] = *(const uint32_t*)&Ks[k0 + 8 + g][2 * c + 8];

            float s1[4] = {0.f, 0.f, 0.f, 0.f};
            float s2[4] = {0.f, 0.f, 0.f, 0.f};
            mma_f16_16816(s1, aq, bk1);
            mma_f16_16816(s2, aq, bk2);

            const float2 a1 = *(const float2*)&am[k0 + 2 * c];
            const float2 a2 = *(const float2*)&am[k0 + 8 + 2 * c];

            // y = s*0.25*log2e + am*log2e; p = 2^y (f16x2, two at a time)
            uint32_t ap[4];
            ap[0] = ex2_f16x2(pack_h2(fmaf(s1[0], EXSC, a1.x), fmaf(s1[1], EXSC, a1.y)));
            ap[1] = ex2_f16x2(pack_h2(fmaf(s1[2], EXSC, a1.x), fmaf(s1[3], EXSC, a1.y)));
            ap[2] = ex2_f16x2(pack_h2(fmaf(s2[0], EXSC, a2.x), fmaf(s2[1], EXSC, a2.y)));
            ap[3] = ex2_f16x2(pack_h2(fmaf(s2[2], EXSC, a2.x), fmaf(s2[3], EXSC, a2.y)));

            // PV: k=16 keys per mma
            uint32_t bv0[2], bv1[2];
            bv0[0] = *(const uint32_t*)&Vt[g    ][k0 + 2 * c    ];
            bv0[1] = *(const uint32_t*)&Vt[g    ][k0 + 8 + 2 * c];
            bv1[0] = *(const uint32_t*)&Vt[g + 8][k0 + 2 * c    ];
            bv1[1] = *(const uint32_t*)&Vt[g + 8][k0 + 8 + 2 * c];

            mma_f16_16816(ctx0, ap, bv0);
            mma_f16_16816(ctx1, ap, bv1);
            mma_f16_16816(sacc, ap, ones2);   // row sums (all cols identical)
        }

        const float inv_lo = 1.0f / sacc[0];
        const float inv_hi = 1.0f / sacc[2];

        const int row_lo = r0 + g;
        const int row_hi = r0 + g + 8;
        if (row_lo < NL) {
            __half* p = g_ctx + ((size_t)b * NL + row_lo) * ND + h * NDH;
            *(uint32_t*)(p + 2 * c)     = pack_h2(ctx0[0] * inv_lo, ctx0[1] * inv_lo);
            *(uint32_t*)(p + 8 + 2 * c) = pack_h2(ctx1[0] * inv_lo, ctx1[1] * inv_lo);
        }
        if (row_hi < NL) {
            __half* p = g_ctx + ((size_t)b * NL + row_hi) * ND + h * NDH;
            *(uint32_t*)(p + 2 * c)     = pack_h2(ctx0[2] * inv_hi, ctx0[3] * inv_hi);
            *(uint32_t*)(p + 8 + 2 * c) = pack_h2(ctx1[2] * inv_hi, ctx1[3] * inv_hi);
        }
    }
}

// ---------------- Kernel 3a: u = Wo @ query^T  (tiny) ----------------
__global__ __launch_bounds__(256)
void u_kernel(const float* __restrict__ Wo, const float* __restrict__ query)
{
    __shared__ float qs[ND];
    const int tid = threadIdx.x;
    qs[tid] = query[tid];
    __syncthreads();
    const float* row = Wo + (size_t)tid * ND;
    float a0 = 0.f, a1 = 0.f, a2 = 0.f, a3 = 0.f;
    #pragma unroll 8
    for (int n = 0; n < ND; n += 4) {
        a0 = fmaf(row[n + 0], qs[n + 0], a0);
        a1 = fmaf(row[n + 1], qs[n + 1], a1);
        a2 = fmaf(row[n + 2], qs[n + 2], a2);
        a3 = fmaf(row[n + 3], qs[n + 3], a3);
    }
    g_u[tid] = (a0 + a1) + (a2 + a3);
}

// ---------------- Kernel 3b: masked softmax pooling + projected epilogue ----------
__global__ __launch_bounds__(256)
void pool_kernel(const float* __restrict__ Wo, const float* __restrict__ bo,
                 const int* __restrict__ his_mask, float* __restrict__ out)
{
    const int b    = blockIdx.x;
    const int tid  = threadIdx.x;
    const int lane = tid & 31;
    const int warp = tid >> 5;

    __shared__ float ps[NL];
    __shared__ float pooled[ND];
    __shared__ float red[8];

    const __half* C = g_ctx + (size_t)b * NL * ND;

    float4 ua = ((const float4*)g_u)[lane * 2];
    float4 ub = ((const float4*)g_u)[lane * 2 + 1];

    for (int l = warp; l < NL; l += 8) {
        const __half2* c2 = (const __half2*)(C + (size_t)l * ND + lane * 8);
        float2 x0 = __half22float2(c2[0]);
        float2 x1 = __half22float2(c2[1]);
        float2 x2 = __half22float2(c2[2]);
        float2 x3 = __half22float2(c2[3]);
        float acc = x0.x * ua.x + x0.y * ua.y + x1.x * ua.z + x1.y * ua.w
                  + x2.x * ub.x + x2.y * ub.y + x3.x * ub.z + x3.y * ub.w;
        #pragma unroll
        for (int o = 16; o; o >>= 1) acc += __shfl_xor_sync(0xffffffffu, acc, o);
        if (lane == 0)
            ps[l] = (his_mask[b * NL + l] > 0) ? acc * 0.0625f : -1e9f;
    }
    __syncthreads();

    float v = (tid < NL) ? ps[tid] : -3.0e38f;
    float mx = v;
    #pragma unroll
    for (int o = 16; o; o >>= 1) mx = fmaxf(mx, __shfl_xor_sync(0xffffffffu, mx, o));
    if (lane == 0) red[warp] = mx;
    __syncthreads();
    float bm = red[0];
    #pragma unroll
    for (int i = 1; i < 8; ++i) bm = fmaxf(bm, red[i]);

    float e = (tid < NL) ? __expf(v - bm) : 0.f;
    float sv = e;
    #pragma unroll
    for (int o = 16; o; o >>= 1) sv += __shfl_xor_sync(0xffffffffu, sv, o);
    __syncthreads();
    if (lane == 0) red[warp] = sv;
    if (tid < NL) ps[tid] = e;
    __syncthreads();
    float tot = (red[0] + red[1]) + (red[2] + red[3])
              + (red[4] + red[5]) + (red[6] + red[7]);
    float inv = 1.0f / tot;

    {
        float a0 = 0.f, a1 = 0.f, a2 = 0.f, a3 = 0.f;
        const __half* Cd = C + tid;
        for (int l = 0; l < NL; l += 4) {
            a0 = fmaf(ps[l + 0], __half2float(Cd[(size_t)(l + 0) * ND]), a0);
            a1 = fmaf(ps[l + 1], __half2float(Cd[(size_t)(l + 1) * ND]), a1);
            a2 = fmaf(ps[l + 2], __half2float(Cd[(size_t)(l + 2) * ND]), a2);
            a3 = fmaf(ps[l + 3], __half2float(Cd[(size_t)(l + 3) * ND]), a3);
        }
        pooled[tid] = ((a0 + a1) + (a2 + a3)) * inv;
    }
    __syncthreads();

    float o = bo[tid];
    const float* Wn = Wo + tid;
    #pragma unroll 8
    for (int d = 0; d < ND; ++d) o = fmaf(pooled[d], Wn[(size_t)d * ND], o);
    out[(size_t)b * ND + tid] = o;
}

// ---------------- launch ----------------
extern "C" void kernel_launch(void* const* d_in, const int* in_sizes, int n_in,
                              void* d_out, int out_size)
{
    const float* news  = (const float*)d_in[0];
    const int*   hmask = (const int*)  d_in[1];
    const float* Wq    = (const float*)d_in[2];
    const float* bq    = (const float*)d_in[3];
    const float* Wk    = (const float*)d_in[4];
    const float* bk    = (const float*)d_in[5];
    const float* Wv    = (const float*)d_in[6];
    const float* bvv   = (const float*)d_in[7];
    const float* Wo    = (const float*)d_in[8];
    const float* bo    = (const float*)d_in[9];
    const float* query = (const float*)d_in[10];
    float* out = (float*)d_out;

    a_convert_kernel<<<(NB * NL * ND) / (8 * 256), 256>>>(news);
    dim3 wgrid(ND, 3);
    w_convert_kernel<<<wgrid, 256>>>(Wq, Wk, Wv);

    dim3 gemm_grid(6, (NB * NL) / 128);            // 6 x 400
    qkv_mma_kernel<<<gemm_grid, 256>>>(bq, bk, bvv);

    dim3 attn_grid(NH, NB);                        // 16 x 256
    attn_kernel<<<attn_grid, ATHREADS>>>(hmask);

    u_kernel<<<1, 256>>>(Wo, query);

    pool_kernel<<<NB, 256>>>(Wo, bo, hmask, out);
}